// round 14
// baseline (speedup 1.0000x reference)
#include <cuda_runtime.h>
#include <math.h>

#define NF   16      // B*F frames
#define S    512
#define S1   513
#define D    256
#define DFF  1024
#define NL   4
#define KNN  50
#define EDIM 42

// ---------------- scratch (device globals; no allocation) ----------------
__device__ float g_src [NF * S1 * D];
__device__ float g_q   [NF * S1 * D];
__device__ float g_k   [NF * S1 * D];
__device__ float g_v   [NF * S1 * D];
__device__ float g_attn[NF * S1 * D];
__device__ float g_tmp1[NF * S1 * DFF];
__device__ int   g_idx [NF * S * 64];     // 50 kNN indices per query (stride 64)

// ---------------- positional encoding + query token ----------------
__global__ void __launch_bounds__(256) pos_kernel(const float* __restrict__ x,
                                                  const float* __restrict__ qe)
{
    int fs = blockIdx.x;              // f*S1 + s
    int f  = fs / S1;
    int s  = fs - f * S1;
    int c  = threadIdx.x;
    float* dst = g_src + (size_t)fs * D;
    if (s == S1 - 1) { dst[c] = qe[c]; return; }
    if (c < 4)       { dst[c] = 0.0f; return; }
    int idx = c - 4;
    int a   = idx / 84;               // axis 0..2
    int r   = idx - a * 84;
    int e   = r >> 1;
    int sc  = r & 1;
    const float bin = 0.002f / 0.015f;
    float xv = x[((size_t)f * S + s) * 3 + a];
    float xq = floorf(xv / bin);
    float dt = powf(10000.0f, (float)e / (float)EDIM);
    float p  = xq / dt;
    dst[c] = sc ? cosf(p) : sinf(p);
}

// ---------------- kNN: warp-per-query register top-50 -> index list ----------------
__global__ void __launch_bounds__(256) knn_kernel(const float* __restrict__ x)
{
    int w = threadIdx.x >> 5, lane = threadIdx.x & 31;
    int qid = blockIdx.x * 8 + w;
    int f = qid >> 9, q = qid & 511;
    const float* xf = x + (size_t)f * S * 3;
    float qx = xf[q * 3], qy = xf[q * 3 + 1], qz = xf[q * 3 + 2];
    float dist[16];
#pragma unroll
    for (int i = 0; i < 16; i++) {
        int k = lane + 32 * i;
        float dx = qx - xf[k * 3];
        float dy = qy - xf[k * 3 + 1];
        float dz = qz - xf[k * 3 + 2];
        dist[i] = __fadd_rn(__fadd_rn(__fmul_rn(dx, dx), __fmul_rn(dy, dy)),
                            __fmul_rn(dz, dz));
    }
    int* orow = g_idx + ((size_t)(f * S + q)) * 64;
    for (int it = 0; it < KNN; it++) {
        float lv = dist[0]; int li = lane;
#pragma unroll
        for (int i = 1; i < 16; i++) {
            if (dist[i] < lv) { lv = dist[i]; li = lane + 32 * i; }
        }
        float v = lv; int idx = li;
#pragma unroll
        for (int o = 16; o; o >>= 1) {
            float ov = __shfl_xor_sync(~0u, v, o);
            int   oi = __shfl_xor_sync(~0u, idx, o);
            if (ov < v || (ov == v && oi < idx)) { v = ov; idx = oi; }
        }
        if (lane == 0) orow[it] = idx;
        int owner = idx & 31, slot = idx >> 5;
        if (lane == owner) {
#pragma unroll
            for (int i = 0; i < 16; i++) if (i == slot) dist[i] = 3.4e38f;
        }
    }
}

// ---------------- tf32 tensor-core GEMM, 2-stage cp.async, templated BM ----------------
__device__ __forceinline__ void mma_tf32(float c[4], const unsigned a[4],
                                         const unsigned b[2])
{
    asm volatile(
        "mma.sync.aligned.m16n8k8.row.col.f32.tf32.tf32.f32 "
        "{%0,%1,%2,%3},{%4,%5,%6,%7},{%8,%9},{%0,%1,%2,%3};\n"
        : "+f"(c[0]), "+f"(c[1]), "+f"(c[2]), "+f"(c[3])
        : "r"(a[0]), "r"(a[1]), "r"(a[2]), "r"(a[3]), "r"(b[0]), "r"(b[1]));
}

__device__ __forceinline__ void cp_async16(unsigned smem_addr, const void* gptr,
                                           bool valid)
{
    int sz = valid ? 16 : 0;
    asm volatile("cp.async.cg.shared.global [%0], [%1], 16, %2;\n"
                 :: "r"(smem_addr), "l"(gptr), "r"(sz));
}

#define ASTR 36
#define BSTR 136
constexpr int gemm_smem_bytes(int BM) { return (2 * BM * ASTR + 2 * 32 * BSTR) * 4; }

template <bool RELU, int BM>
__device__ __forceinline__ void gemm_core(const float* __restrict__ A,
                                          const float* __restrict__ W,
                                          const float* __restrict__ bias,
                                          float* __restrict__ C,
                                          int M, int K, int N,
                                          int bm, int bn)
{
    extern __shared__ float gsm[];
    float* AsB = gsm;                         // [2][BM][36]
    float* BsB = gsm + 2 * BM * ASTR;         // [2][32][136] k-major
    unsigned As_s = (unsigned)__cvta_generic_to_shared(AsB);
    unsigned Bs_s = (unsigned)__cvta_generic_to_shared(BsB);

    constexpr int NP  = BM / 32;              // A cp.async per thread per tile
    constexpr int NMT = BM / 64;              // warp m-tiles (16 rows each)

    const int tid = threadIdx.x;
    const int wid = tid >> 5, lane = tid & 31;
    const int wm = wid & 3, wn = wid >> 2;    // 4x2 warp grid
    const int g = lane >> 2, tg = lane & 3;

    const int acr = tid >> 3, acc4 = (tid & 7) * 4;   // A copy: row, col(float)
    const int bcr = tid >> 5, bcc4 = (tid & 31) * 4;  // B copy: k-row, col(float)

    float c[NMT][8][4];
#pragma unroll
    for (int mt = 0; mt < NMT; mt++)
#pragma unroll
        for (int nt = 0; nt < 8; nt++)
#pragma unroll
            for (int i = 0; i < 4; i++) c[mt][nt][i] = 0.0f;

    // issue tile 0
    {
#pragma unroll
        for (int p = 0; p < NP; p++) {
            int r = acr + 32 * p;
            int gr = bm + r;
            size_t grc = (gr < M) ? (size_t)gr : 0;
            cp_async16(As_s + (unsigned)((r * ASTR + acc4) * 4),
                       A + grc * K + acc4, gr < M);
        }
#pragma unroll
        for (int p = 0; p < 4; p++) {
            int r = bcr + 8 * p;
            cp_async16(Bs_s + (unsigned)((r * BSTR + bcc4) * 4),
                       W + (size_t)r * N + bn + bcc4, true);
        }
        asm volatile("cp.async.commit_group;\n" ::);
    }

    const int nk = K / 32;
    for (int t = 0; t < nk; t++) {
        const int cur = t & 1;
        __syncthreads();   // everyone done computing tile t-1 (buffer cur^1 reusable)
        if (t + 1 < nk) {
            const int k0n = (t + 1) * 32;
            const unsigned abuf = (unsigned)((cur ^ 1) * BM * ASTR * 4);
            const unsigned bbuf = (unsigned)((cur ^ 1) * 32 * BSTR * 4);
#pragma unroll
            for (int p = 0; p < NP; p++) {
                int r = acr + 32 * p;
                int gr = bm + r;
                size_t grc = (gr < M) ? (size_t)gr : 0;
                cp_async16(As_s + abuf + (unsigned)((r * ASTR + acc4) * 4),
                           A + grc * K + k0n + acc4, gr < M);
            }
#pragma unroll
            for (int p = 0; p < 4; p++) {
                int r = bcr + 8 * p;
                cp_async16(Bs_s + bbuf + (unsigned)((r * BSTR + bcc4) * 4),
                           W + (size_t)(k0n + r) * N + bn + bcc4, true);
            }
            asm volatile("cp.async.commit_group;\n" ::);
            asm volatile("cp.async.wait_group 1;\n" ::);
        } else {
            asm volatile("cp.async.wait_group 0;\n" ::);
        }
        __syncthreads();   // tile t visible to all

        const unsigned* As = (const unsigned*)(AsB + cur * BM * ASTR);
        const unsigned* Bs = (const unsigned*)(BsB + cur * 32 * BSTR);
#pragma unroll
        for (int kk = 0; kk < 32; kk += 8) {
            unsigned a[NMT][4], b[8][2];
#pragma unroll
            for (int mt = 0; mt < NMT; mt++) {
                int r0 = wm * (BM / 4) + mt * 16 + g;
                a[mt][0] = As[r0 * ASTR + kk + tg];
                a[mt][1] = As[(r0 + 8) * ASTR + kk + tg];
                a[mt][2] = As[r0 * ASTR + kk + tg + 4];
                a[mt][3] = As[(r0 + 8) * ASTR + kk + tg + 4];
            }
#pragma unroll
            for (int nt = 0; nt < 8; nt++) {
                int nr = wn * 64 + nt * 8 + g;
                b[nt][0] = Bs[(kk + tg) * BSTR + nr];
                b[nt][1] = Bs[(kk + tg + 4) * BSTR + nr];
            }
#pragma unroll
            for (int mt = 0; mt < NMT; mt++)
#pragma unroll
                for (int nt = 0; nt < 8; nt++)
                    mma_tf32(c[mt][nt], a[mt], b[nt]);
        }
    }

#pragma unroll
    for (int mt = 0; mt < NMT; mt++) {
#pragma unroll
        for (int half = 0; half < 2; half++) {
            int row = bm + wm * (BM / 4) + mt * 16 + g + half * 8;
            if (row >= M) continue;
#pragma unroll
            for (int nt = 0; nt < 8; nt++) {
                int col = bn + wn * 64 + nt * 8 + tg * 2;
                float v0 = c[mt][nt][half * 2 + 0] + bias[col];
                float v1 = c[mt][nt][half * 2 + 1] + bias[col + 1];
                if (RELU) { v0 = fmaxf(v0, 0.f); v1 = fmaxf(v1, 0.f); }
                *(float2*)(C + (size_t)row * N + col) = make_float2(v0, v1);
            }
        }
    }
}

template <bool RELU, int BM>
__global__ void __launch_bounds__(256) gemm_tc(const float* __restrict__ A,
                                               const float* __restrict__ W,
                                               const float* __restrict__ bias,
                                               float* __restrict__ C,
                                               int M, int K, int N)
{
    gemm_core<RELU, BM>(A, W, bias, C, M, K, N, blockIdx.y * BM, blockIdx.x * 128);
}

__global__ void __launch_bounds__(256) gemm_qkv(const float* __restrict__ A,
                                                const float* __restrict__ Wq,
                                                const float* __restrict__ Wk,
                                                const float* __restrict__ Wv,
                                                const float* __restrict__ bq,
                                                const float* __restrict__ bk,
                                                const float* __restrict__ bv,
                                                float* __restrict__ Oq,
                                                float* __restrict__ Ok,
                                                float* __restrict__ Ov,
                                                int M)
{
    int z = blockIdx.z;
    const float* W = (z == 0) ? Wq : (z == 1) ? Wk : Wv;
    const float* b = (z == 0) ? bq : (z == 1) ? bk : bv;
    float*       C = (z == 0) ? Oq : (z == 1) ? Ok : Ov;
    gemm_core<false, 128>(A, W, b, C, M, D, D, blockIdx.y * 128, blockIdx.x * 128);
}

// ---------------- sparse attention: stride-36 K stage (float4) ----------------
#define QCH 64      // queries per block
#define NCH (S / QCH)
#define AKS 36      // K row stride in floats
#define ATTN_SMEM_BYTES ((S1 * AKS + 520 + 16 * 104) * 4)

__global__ void __launch_bounds__(512, 2) attn_sparse()
{
    extern __shared__ float asmem[];
    float* Ks   = asmem;                  // [513][36]
    float* sDen = Ks + S1 * AKS;          // [520] dense-row scratch
    float2* kpAll = (float2*)(sDen + 520);// [16 warps][52] (p, key) pairs
    const int h = blockIdx.x, f = blockIdx.y, qc = blockIdx.z;
    const int tid = threadIdx.x, w = tid >> 5, lane = tid & 31;
    float2* kp = kpAll + w * 52;
    const size_t kvbase = ((size_t)f * S1) * D + h * 32;
    const float scale = 0.17677669529663687f;  // 1/sqrt(32)

    {
        const float4* gk4 = (const float4*)(g_k + kvbase);
        for (int i = tid; i < S1 * 8; i += 512) {
            int s = i >> 3, slot = i & 7;
            *(float4*)&Ks[s * AKS + slot * 4] = __ldg(gk4 + s * 64 + slot);
        }
    }
    __syncthreads();

    const int kq = lane >> 3, dg = lane & 7;

#pragma unroll 1
    for (int j = 0; j < QCH / 16; j++) {
        int q = qc * QCH + w * (QCH / 16) + j;

        const float4* qg = (const float4*)(g_q + kvbase + (size_t)q * D);
        float4 qv[8];
#pragma unroll
        for (int i = 0; i < 8; i++) qv[i] = __ldg(qg + i);

        const int* ip = g_idx + ((size_t)(f * S + q)) * 64;
        int keyA = __ldg(ip + lane);
        int j2 = lane + 32;
        bool validB = (j2 <= 50);
        int keyB = (j2 < 50) ? __ldg(ip + j2) : 512;
        int keyBc = validB ? keyB : 0;

        const float4* ka4 = (const float4*)&Ks[keyA * AKS];
        const float4* kb4 = (const float4*)&Ks[keyBc * AKS];
        float dA0 = 0.f, dA1 = 0.f, dB0 = 0.f, dB1 = 0.f;
#pragma unroll
        for (int i = 0; i < 8; i += 2) {
            float4 q0 = qv[i], q1 = qv[i + 1];
            float4 a0 = ka4[i], a1 = ka4[i + 1];
            float4 b0 = kb4[i], b1 = kb4[i + 1];
            dA0 = fmaf(q0.x, a0.x, dA0); dA0 = fmaf(q0.y, a0.y, dA0);
            dA0 = fmaf(q0.z, a0.z, dA0); dA0 = fmaf(q0.w, a0.w, dA0);
            dA1 = fmaf(q1.x, a1.x, dA1); dA1 = fmaf(q1.y, a1.y, dA1);
            dA1 = fmaf(q1.z, a1.z, dA1); dA1 = fmaf(q1.w, a1.w, dA1);
            dB0 = fmaf(q0.x, b0.x, dB0); dB0 = fmaf(q0.y, b0.y, dB0);
            dB0 = fmaf(q0.z, b0.z, dB0); dB0 = fmaf(q0.w, b0.w, dB0);
            dB1 = fmaf(q1.x, b1.x, dB1); dB1 = fmaf(q1.y, b1.y, dB1);
            dB1 = fmaf(q1.z, b1.z, dB1); dB1 = fmaf(q1.w, b1.w, dB1);
        }
        float sA = (dA0 + dA1) * scale;
        float sB = validB ? (dB0 + dB1) * scale : -3.0e38f;
        float m = fmaxf(sA, sB);
#pragma unroll
        for (int o = 16; o; o >>= 1) m = fmaxf(m, __shfl_xor_sync(~0u, m, o));
        float eA = __expf(sA - m);
        float eB = validB ? __expf(sB - m) : 0.f;
        float l = eA + eB;
#pragma unroll
        for (int o = 16; o; o >>= 1) l += __shfl_xor_sync(~0u, l, o);
        float inv = 1.0f / l;

        kp[lane] = make_float2(eA, __int_as_float(keyA));
        if (lane <= 18) kp[32 + lane] = make_float2(eB, __int_as_float(keyBc));
        if (lane == 19) kp[51] = make_float2(0.f, __int_as_float(0));
        __syncwarp();

        float4 acc = make_float4(0.f, 0.f, 0.f, 0.f);
#pragma unroll
        for (int it = 0; it < 13; it++) {
            float2 pk = kp[it * 4 + kq];
            int ky = __float_as_int(pk.y);
            float4 v = *(const float4*)(g_v + kvbase + (size_t)ky * D + dg * 4);
            acc.x = fmaf(pk.x, v.x, acc.x);
            acc.y = fmaf(pk.x, v.y, acc.y);
            acc.z = fmaf(pk.x, v.z, acc.z);
            acc.w = fmaf(pk.x, v.w, acc.w);
        }
#pragma unroll
        for (int o = 8; o <= 16; o <<= 1) {
            acc.x += __shfl_xor_sync(~0u, acc.x, o);
            acc.y += __shfl_xor_sync(~0u, acc.y, o);
            acc.z += __shfl_xor_sync(~0u, acc.z, o);
            acc.w += __shfl_xor_sync(~0u, acc.w, o);
        }
        if (lane < 8) {
            acc.x *= inv; acc.y *= inv; acc.z *= inv; acc.w *= inv;
            *(float4*)(g_attn + kvbase + (size_t)q * D + lane * 4) = acc;
        }
        __syncwarp();
    }

    if (qc == NCH - 1 && w == 0) {
        const float4* qg = (const float4*)(g_q + kvbase + (size_t)512 * D);
        float4 qv[8];
#pragma unroll
        for (int i = 0; i < 8; i++) qv[i] = __ldg(qg + i);

        float m = -3.0e38f;
        for (int it = 0; it < 17; it++) {
            int key = it * 32 + lane;
            if (key < S1) {
                const float4* kr = (const float4*)&Ks[key * AKS];
                float d0 = 0.f, d1 = 0.f;
#pragma unroll
                for (int i = 0; i < 8; i += 2) {
                    float4 q0 = qv[i], k40 = kr[i];
                    float4 q1 = qv[i + 1], k41 = kr[i + 1];
                    d0 = fmaf(q0.x, k40.x, d0); d0 = fmaf(q0.y, k40.y, d0);
                    d0 = fmaf(q0.z, k40.z, d0); d0 = fmaf(q0.w, k40.w, d0);
                    d1 = fmaf(q1.x, k41.x, d1); d1 = fmaf(q1.y, k41.y, d1);
                    d1 = fmaf(q1.z, k41.z, d1); d1 = fmaf(q1.w, k41.w, d1);
                }
                float dot = (d0 + d1) * scale;
                sDen[key] = dot;
                m = fmaxf(m, dot);
            }
        }
#pragma unroll
        for (int o = 16; o; o >>= 1) m = fmaxf(m, __shfl_xor_sync(~0u, m, o));
        __syncwarp();
        float l = 0.f;
        for (int it = 0; it < 17; it++) {
            int key = it * 32 + lane;
            if (key < S1) {
                float e = __expf(sDen[key] - m);
                sDen[key] = e;
                l += e;
            }
        }
#pragma unroll
        for (int o = 16; o; o >>= 1) l += __shfl_xor_sync(~0u, l, o);
        float inv = 1.0f / l;
        __syncwarp();
        float a0 = 0.f, a1 = 0.f;
#pragma unroll 2
        for (int key = 0; key < 512; key += 2) {
            a0 = fmaf(sDen[key],     __ldg(g_v + kvbase + (size_t)key * D + lane), a0);
            a1 = fmaf(sDen[key + 1], __ldg(g_v + kvbase + (size_t)(key + 1) * D + lane), a1);
        }
        a0 = fmaf(sDen[512], __ldg(g_v + kvbase + (size_t)512 * D + lane), a0);
        g_attn[kvbase + (size_t)512 * D + lane] = (a0 + a1) * inv;
    }
}

// ---------------- residual add + layernorm: warp per row, float4 ----------------
__global__ void __launch_bounds__(256) add_ln_kernel(float* __restrict__ src,
                                                     const float* __restrict__ y,
                                                     const float* __restrict__ gg,
                                                     const float* __restrict__ bb,
                                                     int M)
{
    const int w = threadIdx.x >> 5, lane = threadIdx.x & 31;
    const int m = blockIdx.x * 8 + w;
    if (m >= M) return;
    float4* zs = (float4*)(src + (size_t)m * D);
    const float4* ys = (const float4*)(y + (size_t)m * D);
    float4 z0 = zs[lane], z1 = zs[lane + 32];
    float4 y0 = ys[lane], y1 = ys[lane + 32];
    z0.x += y0.x; z0.y += y0.y; z0.z += y0.z; z0.w += y0.w;
    z1.x += y1.x; z1.y += y1.y; z1.z += y1.z; z1.w += y1.w;
    float sum = z0.x + z0.y + z0.z + z0.w + z1.x + z1.y + z1.z + z1.w;
    float sq  = z0.x * z0.x + z0.y * z0.y + z0.z * z0.z + z0.w * z0.w
              + z1.x * z1.x + z1.y * z1.y + z1.z * z1.z + z1.w * z1.w;
#pragma unroll
    for (int o = 16; o; o >>= 1) {
        sum += __shfl_xor_sync(~0u, sum, o);
        sq  += __shfl_xor_sync(~0u, sq, o);
    }
    float mean = sum * (1.0f / D);
    float var  = sq * (1.0f / D) - mean * mean;
    float r = rsqrtf(fmaxf(var, 0.f) + 1e-5f);
    const float4* g4 = (const float4*)gg;
    const float4* b4 = (const float4*)bb;
    float4 ga = g4[lane], gb = g4[lane + 32];
    float4 ba = b4[lane], bc = b4[lane + 32];
    z0.x = (z0.x - mean) * r * ga.x + ba.x;
    z0.y = (z0.y - mean) * r * ga.y + ba.y;
    z0.z = (z0.z - mean) * r * ga.z + ba.z;
    z0.w = (z0.w - mean) * r * ga.w + ba.w;
    z1.x = (z1.x - mean) * r * gb.x + bc.x;
    z1.y = (z1.y - mean) * r * gb.y + bc.y;
    z1.z = (z1.z - mean) * r * gb.z + bc.z;
    z1.w = (z1.w - mean) * r * gb.w + bc.w;
    zs[lane] = z0; zs[lane + 32] = z1;
}

// ---------------- gather query token ----------------
__global__ void out_kernel(float* __restrict__ out)
{
    int f = blockIdx.x, c = threadIdx.x;
    out[f * D + c] = g_src[((size_t)(f * S1 + (S1 - 1))) * D + c];
}

// ---------------- host ----------------
extern "C" void kernel_launch(void* const* d_in, const int* in_sizes, int n_in,
                              void* d_out, int out_size)
{
    const float* x   = (const float*)d_in[0];
    const float* qe  = (const float*)d_in[2];
    const float* Wq  = (const float*)d_in[3];  const float* bq  = (const float*)d_in[4];
    const float* Wk  = (const float*)d_in[5];  const float* bk  = (const float*)d_in[6];
    const float* Wv  = (const float*)d_in[7];  const float* bv  = (const float*)d_in[8];
    const float* Wo  = (const float*)d_in[9];  const float* bo  = (const float*)d_in[10];
    const float* l1g = (const float*)d_in[11]; const float* l1b = (const float*)d_in[12];
    const float* l2g = (const float*)d_in[13]; const float* l2b = (const float*)d_in[14];
    const float* W1  = (const float*)d_in[15]; const float* b1  = (const float*)d_in[16];
    const float* W2  = (const float*)d_in[17]; const float* b2  = (const float*)d_in[18];
    float* out = (float*)d_out;

    float *p_src, *p_q, *p_k, *p_v, *p_attn, *p_tmp1;
    cudaGetSymbolAddress((void**)&p_src,  g_src);
    cudaGetSymbolAddress((void**)&p_q,    g_q);
    cudaGetSymbolAddress((void**)&p_k,    g_k);
    cudaGetSymbolAddress((void**)&p_v,    g_v);
    cudaGetSymbolAddress((void**)&p_attn, g_attn);
    cudaGetSymbolAddress((void**)&p_tmp1, g_tmp1);

    const int smem128 = gemm_smem_bytes(128);
    const int smem64  = gemm_smem_bytes(64);
    cudaFuncSetAttribute(attn_sparse, cudaFuncAttributeMaxDynamicSharedMemorySize,
                         ATTN_SMEM_BYTES);
    cudaFuncSetAttribute(gemm_tc<false, 128>, cudaFuncAttributeMaxDynamicSharedMemorySize,
                         smem128);
    cudaFuncSetAttribute(gemm_tc<true, 128>, cudaFuncAttributeMaxDynamicSharedMemorySize,
                         smem128);
    cudaFuncSetAttribute(gemm_tc<false, 64>, cudaFuncAttributeMaxDynamicSharedMemorySize,
                         smem64);
    cudaFuncSetAttribute(gemm_qkv, cudaFuncAttributeMaxDynamicSharedMemorySize,
                         smem128);

    pos_kernel<<<NF * S1, 256>>>(x, qe);
    knn_kernel<<<NF * S / 8, 256>>>(x);

    const int M = NF * S1;
    dim3 gqkv(D / 128, (M + 127) / 128, 3);
    dim3 g64 (D / 128, (M + 63) / 64);            // BM=64 grids (Wo, W2)
    dim3 g1024(DFF / 128, (M + 127) / 128);
    dim3 gattn(8, NF, NCH);
    int  gln = (M + 7) / 8;

    for (int l = 0; l < NL; l++) {
        size_t wo = (size_t)l * D * D;
        gemm_qkv<<<gqkv, 256, smem128>>>(p_src, Wq + wo, Wk + wo, Wv + wo,
                                bq + l * D, bk + l * D, bv + l * D,
                                p_q, p_k, p_v, M);
        attn_sparse<<<gattn, 512, ATTN_SMEM_BYTES>>>();
        gemm_tc<false, 64><<<g64, 256, smem64>>>(p_attn, Wo + wo, bo + l * D,
                                                 p_tmp1, M, D, D);
        add_ln_kernel<<<gln, 256>>>(p_src, p_tmp1, l1g + l * D, l1b + l * D, M);
        gemm_tc<true, 128><<<g1024, 256, smem128>>>(p_src, W1 + (size_t)l * D * DFF,
                                                    b1 + l * DFF, p_tmp1, M, D, DFF);
        gemm_tc<false, 64><<<g64, 256, smem64>>>(p_tmp1, W2 + (size_t)l * DFF * D,
                                                 b2 + l * D, p_attn, M, DFF, D);
        add_ln_kernel<<<gln, 256>>>(p_src, p_attn, l2g + l * D, l2b + l * D, M);
    }
    out_kernel<<<NF, 256>>>(out);
}

// round 15
// speedup vs baseline: 1.0166x; 1.0166x over previous
#include <cuda_runtime.h>
#include <math.h>

#define NF   16      // B*F frames
#define S    512
#define S1   513
#define D    256
#define DFF  1024
#define NL   4
#define KNN  50
#define EDIM 42

// ---------------- scratch (device globals; no allocation) ----------------
__device__ float g_src [NF * S1 * D];
__device__ float g_q   [NF * S1 * D];
__device__ float g_k   [NF * S1 * D];
__device__ float g_v   [NF * S1 * D];
__device__ float g_attn[NF * S1 * D];
__device__ float g_tmp1[NF * S1 * DFF];
__device__ float g_part[2 * NF * S1 * D];  // split-K partials
__device__ int   g_idx [NF * S * 64];      // 50 kNN indices per query (stride 64)

// ---------------- positional encoding + query token ----------------
__global__ void __launch_bounds__(256) pos_kernel(const float* __restrict__ x,
                                                  const float* __restrict__ qe)
{
    int fs = blockIdx.x;              // f*S1 + s
    int f  = fs / S1;
    int s  = fs - f * S1;
    int c  = threadIdx.x;
    float* dst = g_src + (size_t)fs * D;
    if (s == S1 - 1) { dst[c] = qe[c]; return; }
    if (c < 4)       { dst[c] = 0.0f; return; }
    int idx = c - 4;
    int a   = idx / 84;               // axis 0..2
    int r   = idx - a * 84;
    int e   = r >> 1;
    int sc  = r & 1;
    const float bin = 0.002f / 0.015f;
    float xv = x[((size_t)f * S + s) * 3 + a];
    float xq = floorf(xv / bin);
    float dt = powf(10000.0f, (float)e / (float)EDIM);
    float p  = xq / dt;
    dst[c] = sc ? cosf(p) : sinf(p);
}

// ---------------- kNN: warp-per-query register top-50 -> index list ----------------
__global__ void __launch_bounds__(256) knn_kernel(const float* __restrict__ x)
{
    int w = threadIdx.x >> 5, lane = threadIdx.x & 31;
    int qid = blockIdx.x * 8 + w;
    int f = qid >> 9, q = qid & 511;
    const float* xf = x + (size_t)f * S * 3;
    float qx = xf[q * 3], qy = xf[q * 3 + 1], qz = xf[q * 3 + 2];
    float dist[16];
#pragma unroll
    for (int i = 0; i < 16; i++) {
        int k = lane + 32 * i;
        float dx = qx - xf[k * 3];
        float dy = qy - xf[k * 3 + 1];
        float dz = qz - xf[k * 3 + 2];
        dist[i] = __fadd_rn(__fadd_rn(__fmul_rn(dx, dx), __fmul_rn(dy, dy)),
                            __fmul_rn(dz, dz));
    }
    int* orow = g_idx + ((size_t)(f * S + q)) * 64;
    for (int it = 0; it < KNN; it++) {
        float lv = dist[0]; int li = lane;
#pragma unroll
        for (int i = 1; i < 16; i++) {
            if (dist[i] < lv) { lv = dist[i]; li = lane + 32 * i; }
        }
        float v = lv; int idx = li;
#pragma unroll
        for (int o = 16; o; o >>= 1) {
            float ov = __shfl_xor_sync(~0u, v, o);
            int   oi = __shfl_xor_sync(~0u, idx, o);
            if (ov < v || (ov == v && oi < idx)) { v = ov; idx = oi; }
        }
        if (lane == 0) orow[it] = idx;
        int owner = idx & 31, slot = idx >> 5;
        if (lane == owner) {
#pragma unroll
            for (int i = 0; i < 16; i++) if (i == slot) dist[i] = 3.4e38f;
        }
    }
}

// ---------------- tf32 tensor-core GEMM, 2-stage cp.async ----------------
__device__ __forceinline__ void mma_tf32(float c[4], const unsigned a[4],
                                         const unsigned b[2])
{
    asm volatile(
        "mma.sync.aligned.m16n8k8.row.col.f32.tf32.tf32.f32 "
        "{%0,%1,%2,%3},{%4,%5,%6,%7},{%8,%9},{%0,%1,%2,%3};\n"
        : "+f"(c[0]), "+f"(c[1]), "+f"(c[2]), "+f"(c[3])
        : "r"(a[0]), "r"(a[1]), "r"(a[2]), "r"(a[3]), "r"(b[0]), "r"(b[1]));
}

__device__ __forceinline__ void cp_async16(unsigned smem_addr, const void* gptr,
                                           bool valid)
{
    int sz = valid ? 16 : 0;
    asm volatile("cp.async.cg.shared.global [%0], [%1], 16, %2;\n"
                 :: "r"(smem_addr), "l"(gptr), "r"(sz));
}

#define ASTR 36
#define BSTR 136
#define GEMM_SMEM_BYTES ((2 * 128 * ASTR + 2 * 32 * BSTR) * 4)   // 71680

// C = A[:, kbase:kbase+32*nk] * W[kbase:, bn:bn+128] (+bias if addbias) [+relu]
template <bool RELU>
__device__ __forceinline__ void gemm_core(const float* __restrict__ A,
                                          const float* __restrict__ W,
                                          const float* __restrict__ bias,
                                          float* __restrict__ C,
                                          int M, int Kld, int N,
                                          int bm, int bn,
                                          int kbase, int nk, bool addbias)
{
    extern __shared__ float gsm[];
    float* AsB = gsm;                         // [2][128][36]
    float* BsB = gsm + 2 * 128 * ASTR;        // [2][32][136] k-major
    unsigned As_s = (unsigned)__cvta_generic_to_shared(AsB);
    unsigned Bs_s = (unsigned)__cvta_generic_to_shared(BsB);

    const int tid = threadIdx.x;
    const int wid = tid >> 5, lane = tid & 31;
    const int wm = wid & 3, wn = wid >> 2;    // 4x2 warp grid; tile 32x64
    const int g = lane >> 2, tg = lane & 3;

    const int acr = tid >> 3, acc4 = (tid & 7) * 4;   // A copy: row, col(float)
    const int bcr = tid >> 5, bcc4 = (tid & 31) * 4;  // B copy: k-row, col(float)

    float c[2][8][4];
#pragma unroll
    for (int mt = 0; mt < 2; mt++)
#pragma unroll
        for (int nt = 0; nt < 8; nt++)
#pragma unroll
            for (int i = 0; i < 4; i++) c[mt][nt][i] = 0.0f;

    // issue tile 0
    {
#pragma unroll
        for (int p = 0; p < 4; p++) {
            int r = acr + 32 * p;
            int gr = bm + r;
            size_t grc = (gr < M) ? (size_t)gr : 0;
            cp_async16(As_s + (unsigned)((r * ASTR + acc4) * 4),
                       A + grc * Kld + kbase + acc4, gr < M);
        }
#pragma unroll
        for (int p = 0; p < 4; p++) {
            int r = bcr + 8 * p;
            cp_async16(Bs_s + (unsigned)((r * BSTR + bcc4) * 4),
                       W + (size_t)(kbase + r) * N + bn + bcc4, true);
        }
        asm volatile("cp.async.commit_group;\n" ::);
    }

    for (int t = 0; t < nk; t++) {
        const int cur = t & 1;
        __syncthreads();   // everyone done computing tile t-1 (buffer cur^1 reusable)
        if (t + 1 < nk) {
            const int k0n = kbase + (t + 1) * 32;
            const unsigned abuf = (unsigned)((cur ^ 1) * 128 * ASTR * 4);
            const unsigned bbuf = (unsigned)((cur ^ 1) * 32 * BSTR * 4);
#pragma unroll
            for (int p = 0; p < 4; p++) {
                int r = acr + 32 * p;
                int gr = bm + r;
                size_t grc = (gr < M) ? (size_t)gr : 0;
                cp_async16(As_s + abuf + (unsigned)((r * ASTR + acc4) * 4),
                           A + grc * Kld + k0n + acc4, gr < M);
            }
#pragma unroll
            for (int p = 0; p < 4; p++) {
                int r = bcr + 8 * p;
                cp_async16(Bs_s + bbuf + (unsigned)((r * BSTR + bcc4) * 4),
                           W + (size_t)(k0n + r) * N + bn + bcc4, true);
            }
            asm volatile("cp.async.commit_group;\n" ::);
            asm volatile("cp.async.wait_group 1;\n" ::);
        } else {
            asm volatile("cp.async.wait_group 0;\n" ::);
        }
        __syncthreads();   // tile t visible to all

        const unsigned* As = (const unsigned*)(AsB + cur * 128 * ASTR);
        const unsigned* Bs = (const unsigned*)(BsB + cur * 32 * BSTR);
#pragma unroll
        for (int kk = 0; kk < 32; kk += 8) {
            unsigned a[2][4], b[8][2];
#pragma unroll
            for (int mt = 0; mt < 2; mt++) {
                int r0 = wm * 32 + mt * 16 + g;
                a[mt][0] = As[r0 * ASTR + kk + tg];
                a[mt][1] = As[(r0 + 8) * ASTR + kk + tg];
                a[mt][2] = As[r0 * ASTR + kk + tg + 4];
                a[mt][3] = As[(r0 + 8) * ASTR + kk + tg + 4];
            }
#pragma unroll
            for (int nt = 0; nt < 8; nt++) {
                int nr = wn * 64 + nt * 8 + g;
                b[nt][0] = Bs[(kk + tg) * BSTR + nr];
                b[nt][1] = Bs[(kk + tg + 4) * BSTR + nr];
            }
#pragma unroll
            for (int mt = 0; mt < 2; mt++)
#pragma unroll
                for (int nt = 0; nt < 8; nt++)
                    mma_tf32(c[mt][nt], a[mt], b[nt]);
        }
    }

#pragma unroll
    for (int mt = 0; mt < 2; mt++) {
#pragma unroll
        for (int half = 0; half < 2; half++) {
            int row = bm + wm * 32 + mt * 16 + g + half * 8;
            if (row >= M) continue;
#pragma unroll
            for (int nt = 0; nt < 8; nt++) {
                int col = bn + wn * 64 + nt * 8 + tg * 2;
                float bb0 = addbias ? bias[col] : 0.f;
                float bb1 = addbias ? bias[col + 1] : 0.f;
                float v0 = c[mt][nt][half * 2 + 0] + bb0;
                float v1 = c[mt][nt][half * 2 + 1] + bb1;
                if (RELU) { v0 = fmaxf(v0, 0.f); v1 = fmaxf(v1, 0.f); }
                *(float2*)(C + (size_t)row * N + col) = make_float2(v0, v1);
            }
        }
    }
}

template <bool RELU>
__global__ void __launch_bounds__(256) gemm_tc(const float* __restrict__ A,
                                               const float* __restrict__ W,
                                               const float* __restrict__ bias,
                                               float* __restrict__ C,
                                               int M, int K, int N)
{
    gemm_core<RELU>(A, W, bias, C, M, K, N, blockIdx.y * 128, blockIdx.x * 128,
                    0, K / 32, true);
}

// split-K: blockIdx.z selects K half; partial z written to C + z*M*N
__global__ void __launch_bounds__(256) gemm_splitk(const float* __restrict__ A,
                                                   const float* __restrict__ W,
                                                   const float* __restrict__ bias,
                                                   float* __restrict__ C,
                                                   int M, int K, int N)
{
    int z = blockIdx.z;
    int ks = K / 2;
    gemm_core<false>(A, W, bias, C + (size_t)z * M * N, M, K, N,
                     blockIdx.y * 128, blockIdx.x * 128,
                     z * ks, ks / 32, z == 0);
}

__global__ void __launch_bounds__(256) gemm_qkv(const float* __restrict__ A,
                                                const float* __restrict__ Wq,
                                                const float* __restrict__ Wk,
                                                const float* __restrict__ Wv,
                                                const float* __restrict__ bq,
                                                const float* __restrict__ bk,
                                                const float* __restrict__ bv,
                                                float* __restrict__ Oq,
                                                float* __restrict__ Ok,
                                                float* __restrict__ Ov,
                                                int M)
{
    int z = blockIdx.z;
    const float* W = (z == 0) ? Wq : (z == 1) ? Wk : Wv;
    const float* b = (z == 0) ? bq : (z == 1) ? bk : bv;
    float*       C = (z == 0) ? Oq : (z == 1) ? Ok : Ov;
    gemm_core<false>(A, W, b, C, M, D, D, blockIdx.y * 128, blockIdx.x * 128,
                     0, D / 32, true);
}

// ---------------- sparse attention: stride-36 K stage (float4) ----------------
#define QCH 64      // queries per block
#define NCH (S / QCH)
#define AKS 36      // K row stride in floats
#define ATTN_SMEM_BYTES ((S1 * AKS + 520 + 16 * 104) * 4)

__global__ void __launch_bounds__(512, 2) attn_sparse()
{
    extern __shared__ float asmem[];
    float* Ks   = asmem;                  // [513][36]
    float* sDen = Ks + S1 * AKS;          // [520] dense-row scratch
    float2* kpAll = (float2*)(sDen + 520);// [16 warps][52] (p, key) pairs
    const int h = blockIdx.x, f = blockIdx.y, qc = blockIdx.z;
    const int tid = threadIdx.x, w = tid >> 5, lane = tid & 31;
    float2* kp = kpAll + w * 52;
    const size_t kvbase = ((size_t)f * S1) * D + h * 32;
    const float scale = 0.17677669529663687f;  // 1/sqrt(32)

    {
        const float4* gk4 = (const float4*)(g_k + kvbase);
        for (int i = tid; i < S1 * 8; i += 512) {
            int s = i >> 3, slot = i & 7;
            *(float4*)&Ks[s * AKS + slot * 4] = __ldg(gk4 + s * 64 + slot);
        }
    }
    __syncthreads();

    const int kq = lane >> 3, dg = lane & 7;

#pragma unroll 1
    for (int j = 0; j < QCH / 16; j++) {
        int q = qc * QCH + w * (QCH / 16) + j;

        const float4* qg = (const float4*)(g_q + kvbase + (size_t)q * D);
        float4 qv[8];
#pragma unroll
        for (int i = 0; i < 8; i++) qv[i] = __ldg(qg + i);

        const int* ip = g_idx + ((size_t)(f * S + q)) * 64;
        int keyA = __ldg(ip + lane);
        int j2 = lane + 32;
        bool validB = (j2 <= 50);
        int keyB = (j2 < 50) ? __ldg(ip + j2) : 512;
        int keyBc = validB ? keyB : 0;

        const float4* ka4 = (const float4*)&Ks[keyA * AKS];
        const float4* kb4 = (const float4*)&Ks[keyBc * AKS];
        float dA0 = 0.f, dA1 = 0.f, dB0 = 0.f, dB1 = 0.f;
#pragma unroll
        for (int i = 0; i < 8; i += 2) {
            float4 q0 = qv[i], q1 = qv[i + 1];
            float4 a0 = ka4[i], a1 = ka4[i + 1];
            float4 b0 = kb4[i], b1 = kb4[i + 1];
            dA0 = fmaf(q0.x, a0.x, dA0); dA0 = fmaf(q0.y, a0.y, dA0);
            dA0 = fmaf(q0.z, a0.z, dA0); dA0 = fmaf(q0.w, a0.w, dA0);
            dA1 = fmaf(q1.x, a1.x, dA1); dA1 = fmaf(q1.y, a1.y, dA1);
            dA1 = fmaf(q1.z, a1.z, dA1); dA1 = fmaf(q1.w, a1.w, dA1);
            dB0 = fmaf(q0.x, b0.x, dB0); dB0 = fmaf(q0.y, b0.y, dB0);
            dB0 = fmaf(q0.z, b0.z, dB0); dB0 = fmaf(q0.w, b0.w, dB0);
            dB1 = fmaf(q1.x, b1.x, dB1); dB1 = fmaf(q1.y, b1.y, dB1);
            dB1 = fmaf(q1.z, b1.z, dB1); dB1 = fmaf(q1.w, b1.w, dB1);
        }
        float sA = (dA0 + dA1) * scale;
        float sB = validB ? (dB0 + dB1) * scale : -3.0e38f;
        float m = fmaxf(sA, sB);
#pragma unroll
        for (int o = 16; o; o >>= 1) m = fmaxf(m, __shfl_xor_sync(~0u, m, o));
        float eA = __expf(sA - m);
        float eB = validB ? __expf(sB - m) : 0.f;
        float l = eA + eB;
#pragma unroll
        for (int o = 16; o; o >>= 1) l += __shfl_xor_sync(~0u, l, o);
        float inv = 1.0f / l;

        kp[lane] = make_float2(eA, __int_as_float(keyA));
        if (lane <= 18) kp[32 + lane] = make_float2(eB, __int_as_float(keyBc));
        if (lane == 19) kp[51] = make_float2(0.f, __int_as_float(0));
        __syncwarp();

        float4 acc = make_float4(0.f, 0.f, 0.f, 0.f);
#pragma unroll
        for (int it = 0; it < 13; it++) {
            float2 pk = kp[it * 4 + kq];
            int ky = __float_as_int(pk.y);
            float4 v = *(const float4*)(g_v + kvbase + (size_t)ky * D + dg * 4);
            acc.x = fmaf(pk.x, v.x, acc.x);
            acc.y = fmaf(pk.x, v.y, acc.y);
            acc.z = fmaf(pk.x, v.z, acc.z);
            acc.w = fmaf(pk.x, v.w, acc.w);
        }
#pragma unroll
        for (int o = 8; o <= 16; o <<= 1) {
            acc.x += __shfl_xor_sync(~0u, acc.x, o);
            acc.y += __shfl_xor_sync(~0u, acc.y, o);
            acc.z += __shfl_xor_sync(~0u, acc.z, o);
            acc.w += __shfl_xor_sync(~0u, acc.w, o);
        }
        if (lane < 8) {
            acc.x *= inv; acc.y *= inv; acc.z *= inv; acc.w *= inv;
            *(float4*)(g_attn + kvbase + (size_t)q * D + lane * 4) = acc;
        }
        __syncwarp();
    }

    if (qc == NCH - 1 && w == 0) {
        const float4* qg = (const float4*)(g_q + kvbase + (size_t)512 * D);
        float4 qv[8];
#pragma unroll
        for (int i = 0; i < 8; i++) qv[i] = __ldg(qg + i);

        float m = -3.0e38f;
        for (int it = 0; it < 17; it++) {
            int key = it * 32 + lane;
            if (key < S1) {
                const float4* kr = (const float4*)&Ks[key * AKS];
                float d0 = 0.f, d1 = 0.f;
#pragma unroll
                for (int i = 0; i < 8; i += 2) {
                    float4 q0 = qv[i], k40 = kr[i];
                    float4 q1 = qv[i + 1], k41 = kr[i + 1];
                    d0 = fmaf(q0.x, k40.x, d0); d0 = fmaf(q0.y, k40.y, d0);
                    d0 = fmaf(q0.z, k40.z, d0); d0 = fmaf(q0.w, k40.w, d0);
                    d1 = fmaf(q1.x, k41.x, d1); d1 = fmaf(q1.y, k41.y, d1);
                    d1 = fmaf(q1.z, k41.z, d1); d1 = fmaf(q1.w, k41.w, d1);
                }
                float dot = (d0 + d1) * scale;
                sDen[key] = dot;
                m = fmaxf(m, dot);
            }
        }
#pragma unroll
        for (int o = 16; o; o >>= 1) m = fmaxf(m, __shfl_xor_sync(~0u, m, o));
        __syncwarp();
        float l = 0.f;
        for (int it = 0; it < 17; it++) {
            int key = it * 32 + lane;
            if (key < S1) {
                float e = __expf(sDen[key] - m);
                sDen[key] = e;
                l += e;
            }
        }
#pragma unroll
        for (int o = 16; o; o >>= 1) l += __shfl_xor_sync(~0u, l, o);
        float inv = 1.0f / l;
        __syncwarp();
        float a0 = 0.f, a1 = 0.f;
#pragma unroll 2
        for (int key = 0; key < 512; key += 2) {
            a0 = fmaf(sDen[key],     __ldg(g_v + kvbase + (size_t)key * D + lane), a0);
            a1 = fmaf(sDen[key + 1], __ldg(g_v + kvbase + (size_t)(key + 1) * D + lane), a1);
        }
        a0 = fmaf(sDen[512], __ldg(g_v + kvbase + (size_t)512 * D + lane), a0);
        g_attn[kvbase + (size_t)512 * D + lane] = (a0 + a1) * inv;
    }
}

// ---------------- residual add (two partials) + layernorm ----------------
__global__ void __launch_bounds__(256) add_ln3_kernel(float* __restrict__ src,
                                                      const float* __restrict__ y0p,
                                                      const float* __restrict__ y1p,
                                                      const float* __restrict__ gg,
                                                      const float* __restrict__ bb,
                                                      int M)
{
    const int w = threadIdx.x >> 5, lane = threadIdx.x & 31;
    const int m = blockIdx.x * 8 + w;
    if (m >= M) return;
    float4* zs = (float4*)(src + (size_t)m * D);
    const float4* ys0 = (const float4*)(y0p + (size_t)m * D);
    const float4* ys1 = (const float4*)(y1p + (size_t)m * D);
    float4 z0 = zs[lane], z1 = zs[lane + 32];
    float4 a0 = ys0[lane], a1 = ys0[lane + 32];
    float4 b0 = ys1[lane], b1 = ys1[lane + 32];
    z0.x += a0.x + b0.x; z0.y += a0.y + b0.y;
    z0.z += a0.z + b0.z; z0.w += a0.w + b0.w;
    z1.x += a1.x + b1.x; z1.y += a1.y + b1.y;
    z1.z += a1.z + b1.z; z1.w += a1.w + b1.w;
    float sum = z0.x + z0.y + z0.z + z0.w + z1.x + z1.y + z1.z + z1.w;
    float sq  = z0.x * z0.x + z0.y * z0.y + z0.z * z0.z + z0.w * z0.w
              + z1.x * z1.x + z1.y * z1.y + z1.z * z1.z + z1.w * z1.w;
#pragma unroll
    for (int o = 16; o; o >>= 1) {
        sum += __shfl_xor_sync(~0u, sum, o);
        sq  += __shfl_xor_sync(~0u, sq, o);
    }
    float mean = sum * (1.0f / D);
    float var  = sq * (1.0f / D) - mean * mean;
    float r = rsqrtf(fmaxf(var, 0.f) + 1e-5f);
    const float4* g4 = (const float4*)gg;
    const float4* b4 = (const float4*)bb;
    float4 ga = g4[lane], gb = g4[lane + 32];
    float4 ba = b4[lane], bc = b4[lane + 32];
    z0.x = (z0.x - mean) * r * ga.x + ba.x;
    z0.y = (z0.y - mean) * r * ga.y + ba.y;
    z0.z = (z0.z - mean) * r * ga.z + ba.z;
    z0.w = (z0.w - mean) * r * ga.w + ba.w;
    z1.x = (z1.x - mean) * r * gb.x + bc.x;
    z1.y = (z1.y - mean) * r * gb.y + bc.y;
    z1.z = (z1.z - mean) * r * gb.z + bc.z;
    z1.w = (z1.w - mean) * r * gb.w + bc.w;
    zs[lane] = z0; zs[lane + 32] = z1;
}

// ---------------- gather query token ----------------
__global__ void out_kernel(float* __restrict__ out)
{
    int f = blockIdx.x, c = threadIdx.x;
    out[f * D + c] = g_src[((size_t)(f * S1 + (S1 - 1))) * D + c];
}

// ---------------- host ----------------
extern "C" void kernel_launch(void* const* d_in, const int* in_sizes, int n_in,
                              void* d_out, int out_size)
{
    const float* x   = (const float*)d_in[0];
    const float* qe  = (const float*)d_in[2];
    const float* Wq  = (const float*)d_in[3];  const float* bq  = (const float*)d_in[4];
    const float* Wk  = (const float*)d_in[5];  const float* bk  = (const float*)d_in[6];
    const float* Wv  = (const float*)d_in[7];  const float* bv  = (const float*)d_in[8];
    const float* Wo  = (const float*)d_in[9];  const float* bo  = (const float*)d_in[10];
    const float* l1g = (const float*)d_in[11]; const float* l1b = (const float*)d_in[12];
    const float* l2g = (const float*)d_in[13]; const float* l2b = (const float*)d_in[14];
    const float* W1  = (const float*)d_in[15]; const float* b1  = (const float*)d_in[16];
    const float* W2  = (const float*)d_in[17]; const float* b2  = (const float*)d_in[18];
    float* out = (float*)d_out;

    float *p_src, *p_q, *p_k, *p_v, *p_attn, *p_tmp1, *p_part;
    cudaGetSymbolAddress((void**)&p_src,  g_src);
    cudaGetSymbolAddress((void**)&p_q,    g_q);
    cudaGetSymbolAddress((void**)&p_k,    g_k);
    cudaGetSymbolAddress((void**)&p_v,    g_v);
    cudaGetSymbolAddress((void**)&p_attn, g_attn);
    cudaGetSymbolAddress((void**)&p_tmp1, g_tmp1);
    cudaGetSymbolAddress((void**)&p_part, g_part);

    cudaFuncSetAttribute(attn_sparse, cudaFuncAttributeMaxDynamicSharedMemorySize,
                         ATTN_SMEM_BYTES);
    cudaFuncSetAttribute(gemm_tc<false>, cudaFuncAttributeMaxDynamicSharedMemorySize,
                         GEMM_SMEM_BYTES);
    cudaFuncSetAttribute(gemm_tc<true>, cudaFuncAttributeMaxDynamicSharedMemorySize,
                         GEMM_SMEM_BYTES);
    cudaFuncSetAttribute(gemm_splitk, cudaFuncAttributeMaxDynamicSharedMemorySize,
                         GEMM_SMEM_BYTES);
    cudaFuncSetAttribute(gemm_qkv, cudaFuncAttributeMaxDynamicSharedMemorySize,
                         GEMM_SMEM_BYTES);

    pos_kernel<<<NF * S1, 256>>>(x, qe);
    knn_kernel<<<NF * S / 8, 256>>>(x);

    const int M = NF * S1;
    dim3 gqkv(D / 128, (M + 127) / 128, 3);
    dim3 gsplit(D / 128, (M + 127) / 128, 2);
    dim3 g1024(DFF / 128, (M + 127) / 128);
    dim3 gattn(8, NF, NCH);
    int  gln = (M + 7) / 8;
    const size_t pstride = (size_t)M * D;

    for (int l = 0; l < NL; l++) {
        size_t wo = (size_t)l * D * D;
        gemm_qkv<<<gqkv, 256, GEMM_SMEM_BYTES>>>(p_src, Wq + wo, Wk + wo, Wv + wo,
                                bq + l * D, bk + l * D, bv + l * D,
                                p_q, p_k, p_v, M);
        attn_sparse<<<gattn, 512, ATTN_SMEM_BYTES>>>();
        gemm_splitk<<<gsplit, 256, GEMM_SMEM_BYTES>>>(p_attn, Wo + wo, bo + l * D,
                                                      p_part, M, D, D);
        add_ln3_kernel<<<gln, 256>>>(p_src, p_part, p_part + pstride,
                                     l1g + l * D, l1b + l * D, M);
        gemm_tc<true><<<g1024, 256, GEMM_SMEM_BYTES>>>(p_src, W1 + (size_t)l * D * DFF,
                                                       b1 + l * DFF, p_tmp1, M, D, DFF);
        gemm_splitk<<<gsplit, 256, GEMM_SMEM_BYTES>>>(p_tmp1, W2 + (size_t)l * DFF * D,
                                                      b2 + l * D, p_part, M, DFF, D);
        add_ln3_kernel<<<gln, 256>>>(p_src, p_part, p_part + pstride,
                                     l2g + l * D, l2b + l * D, M);
    }
    out_kernel<<<NF, 256>>>(out);
}

// round 16
// speedup vs baseline: 1.0388x; 1.0218x over previous
#include <cuda_runtime.h>
#include <math.h>

#define NF   16      // B*F frames
#define S    512
#define S1   513
#define D    256
#define DFF  1024
#define NL   4
#define KNN  50
#define EDIM 42

// ---------------- scratch (device globals; no allocation) ----------------
__device__ float g_src [NF * S1 * D];
__device__ float g_q   [NF * S1 * D];
__device__ float g_k   [NF * S1 * D];
__device__ float g_v   [NF * S1 * D];
__device__ float g_attn[NF * S1 * D];
__device__ float g_tmp1[NF * S1 * DFF];
__device__ int   g_idx [NF * S * 64];     // 50 kNN indices per query (stride 64)

// ---------------- positional encoding + query token ----------------
__global__ void __launch_bounds__(256) pos_kernel(const float* __restrict__ x,
                                                  const float* __restrict__ qe)
{
    int fs = blockIdx.x;              // f*S1 + s
    int f  = fs / S1;
    int s  = fs - f * S1;
    int c  = threadIdx.x;
    float* dst = g_src + (size_t)fs * D;
    if (s == S1 - 1) { dst[c] = qe[c]; return; }
    if (c < 4)       { dst[c] = 0.0f; return; }
    int idx = c - 4;
    int a   = idx / 84;               // axis 0..2
    int r   = idx - a * 84;
    int e   = r >> 1;
    int sc  = r & 1;
    const float bin = 0.002f / 0.015f;
    float xv = x[((size_t)f * S + s) * 3 + a];
    float xq = floorf(xv / bin);
    float dt = powf(10000.0f, (float)e / (float)EDIM);
    float p  = xq / dt;
    dst[c] = sc ? cosf(p) : sinf(p);
}

// ---------------- kNN: warp-per-query register top-50 -> index list ----------------
__global__ void __launch_bounds__(256) knn_kernel(const float* __restrict__ x)
{
    int w = threadIdx.x >> 5, lane = threadIdx.x & 31;
    int qid = blockIdx.x * 8 + w;
    int f = qid >> 9, q = qid & 511;
    const float* xf = x + (size_t)f * S * 3;
    float qx = xf[q * 3], qy = xf[q * 3 + 1], qz = xf[q * 3 + 2];
    float dist[16];
#pragma unroll
    for (int i = 0; i < 16; i++) {
        int k = lane + 32 * i;
        float dx = qx - xf[k * 3];
        float dy = qy - xf[k * 3 + 1];
        float dz = qz - xf[k * 3 + 2];
        dist[i] = __fadd_rn(__fadd_rn(__fmul_rn(dx, dx), __fmul_rn(dy, dy)),
                            __fmul_rn(dz, dz));
    }
    int* orow = g_idx + ((size_t)(f * S + q)) * 64;
    for (int it = 0; it < KNN; it++) {
        float lv = dist[0]; int li = lane;
#pragma unroll
        for (int i = 1; i < 16; i++) {
            if (dist[i] < lv) { lv = dist[i]; li = lane + 32 * i; }
        }
        float v = lv; int idx = li;
#pragma unroll
        for (int o = 16; o; o >>= 1) {
            float ov = __shfl_xor_sync(~0u, v, o);
            int   oi = __shfl_xor_sync(~0u, idx, o);
            if (ov < v || (ov == v && oi < idx)) { v = ov; idx = oi; }
        }
        if (lane == 0) orow[it] = idx;
        int owner = idx & 31, slot = idx >> 5;
        if (lane == owner) {
#pragma unroll
            for (int i = 0; i < 16; i++) if (i == slot) dist[i] = 3.4e38f;
        }
    }
}

// ---------------- tf32 tensor-core GEMM, 2-stage cp.async (R12 config) ----------------
__device__ __forceinline__ void mma_tf32(float c[4], const unsigned a[4],
                                         const unsigned b[2])
{
    asm volatile(
        "mma.sync.aligned.m16n8k8.row.col.f32.tf32.tf32.f32 "
        "{%0,%1,%2,%3},{%4,%5,%6,%7},{%8,%9},{%0,%1,%2,%3};\n"
        : "+f"(c[0]), "+f"(c[1]), "+f"(c[2]), "+f"(c[3])
        : "r"(a[0]), "r"(a[1]), "r"(a[2]), "r"(a[3]), "r"(b[0]), "r"(b[1]));
}

__device__ __forceinline__ void cp_async16(unsigned smem_addr, const void* gptr,
                                           bool valid)
{
    int sz = valid ? 16 : 0;
    asm volatile("cp.async.cg.shared.global [%0], [%1], 16, %2;\n"
                 :: "r"(smem_addr), "l"(gptr), "r"(sz));
}

#define ASTR 36
#define BSTR 136
#define GEMM_SMEM_BYTES ((2 * 128 * ASTR + 2 * 32 * BSTR) * 4)   // 71680

template <bool RELU>
__device__ __forceinline__ void gemm_core(const float* __restrict__ A,
                                          const float* __restrict__ W,
                                          const float* __restrict__ bias,
                                          float* __restrict__ C,
                                          int M, int K, int N,
                                          int bm, int bn)
{
    extern __shared__ float gsm[];
    float* AsB = gsm;                         // [2][128][36]
    float* BsB = gsm + 2 * 128 * ASTR;        // [2][32][136] k-major
    unsigned As_s = (unsigned)__cvta_generic_to_shared(AsB);
    unsigned Bs_s = (unsigned)__cvta_generic_to_shared(BsB);

    const int tid = threadIdx.x;
    const int wid = tid >> 5, lane = tid & 31;
    const int wm = wid & 3, wn = wid >> 2;    // 4x2 warp grid; tile 32x64
    const int g = lane >> 2, tg = lane & 3;

    const int acr = tid >> 3, acc4 = (tid & 7) * 4;   // A copy: row, col(float)
    const int bcr = tid >> 5, bcc4 = (tid & 31) * 4;  // B copy: k-row, col(float)

    float c[2][8][4];
#pragma unroll
    for (int mt = 0; mt < 2; mt++)
#pragma unroll
        for (int nt = 0; nt < 8; nt++)
#pragma unroll
            for (int i = 0; i < 4; i++) c[mt][nt][i] = 0.0f;

    // issue tile 0
    {
#pragma unroll
        for (int p = 0; p < 4; p++) {
            int r = acr + 32 * p;
            int gr = bm + r;
            size_t grc = (gr < M) ? (size_t)gr : 0;
            cp_async16(As_s + (unsigned)((r * ASTR + acc4) * 4),
                       A + grc * K + acc4, gr < M);
        }
#pragma unroll
        for (int p = 0; p < 4; p++) {
            int r = bcr + 8 * p;
            cp_async16(Bs_s + (unsigned)((r * BSTR + bcc4) * 4),
                       W + (size_t)r * N + bn + bcc4, true);
        }
        asm volatile("cp.async.commit_group;\n" ::);
    }

    const int nk = K / 32;
    for (int t = 0; t < nk; t++) {
        const int cur = t & 1;
        __syncthreads();   // everyone done computing tile t-1 (buffer cur^1 reusable)
        if (t + 1 < nk) {
            const int k0n = (t + 1) * 32;
            const unsigned abuf = (unsigned)((cur ^ 1) * 128 * ASTR * 4);
            const unsigned bbuf = (unsigned)((cur ^ 1) * 32 * BSTR * 4);
#pragma unroll
            for (int p = 0; p < 4; p++) {
                int r = acr + 32 * p;
                int gr = bm + r;
                size_t grc = (gr < M) ? (size_t)gr : 0;
                cp_async16(As_s + abuf + (unsigned)((r * ASTR + acc4) * 4),
                           A + grc * K + k0n + acc4, gr < M);
            }
#pragma unroll
            for (int p = 0; p < 4; p++) {
                int r = bcr + 8 * p;
                cp_async16(Bs_s + bbuf + (unsigned)((r * BSTR + bcc4) * 4),
                           W + (size_t)(k0n + r) * N + bn + bcc4, true);
            }
            asm volatile("cp.async.commit_group;\n" ::);
            asm volatile("cp.async.wait_group 1;\n" ::);
        } else {
            asm volatile("cp.async.wait_group 0;\n" ::);
        }
        __syncthreads();   // tile t visible to all

        const unsigned* As = (const unsigned*)(AsB + cur * 128 * ASTR);
        const unsigned* Bs = (const unsigned*)(BsB + cur * 32 * BSTR);
#pragma unroll
        for (int kk = 0; kk < 32; kk += 8) {
            unsigned a[2][4], b[8][2];
#pragma unroll
            for (int mt = 0; mt < 2; mt++) {
                int r0 = wm * 32 + mt * 16 + g;
                a[mt][0] = As[r0 * ASTR + kk + tg];
                a[mt][1] = As[(r0 + 8) * ASTR + kk + tg];
                a[mt][2] = As[r0 * ASTR + kk + tg + 4];
                a[mt][3] = As[(r0 + 8) * ASTR + kk + tg + 4];
            }
#pragma unroll
            for (int nt = 0; nt < 8; nt++) {
                int nr = wn * 64 + nt * 8 + g;
                b[nt][0] = Bs[(kk + tg) * BSTR + nr];
                b[nt][1] = Bs[(kk + tg + 4) * BSTR + nr];
            }
#pragma unroll
            for (int mt = 0; mt < 2; mt++)
#pragma unroll
                for (int nt = 0; nt < 8; nt++)
                    mma_tf32(c[mt][nt], a[mt], b[nt]);
        }
    }

#pragma unroll
    for (int mt = 0; mt < 2; mt++) {
#pragma unroll
        for (int half = 0; half < 2; half++) {
            int row = bm + wm * 32 + mt * 16 + g + half * 8;
            if (row >= M) continue;
#pragma unroll
            for (int nt = 0; nt < 8; nt++) {
                int col = bn + wn * 64 + nt * 8 + tg * 2;
                float v0 = c[mt][nt][half * 2 + 0] + bias[col];
                float v1 = c[mt][nt][half * 2 + 1] + bias[col + 1];
                if (RELU) { v0 = fmaxf(v0, 0.f); v1 = fmaxf(v1, 0.f); }
                *(float2*)(C + (size_t)row * N + col) = make_float2(v0, v1);
            }
        }
    }
}

template <bool RELU>
__global__ void __launch_bounds__(256) gemm_tc(const float* __restrict__ A,
                                               const float* __restrict__ W,
                                               const float* __restrict__ bias,
                                               float* __restrict__ C,
                                               int M, int K, int N)
{
    gemm_core<RELU>(A, W, bias, C, M, K, N, blockIdx.y * 128, blockIdx.x * 128);
}

__global__ void __launch_bounds__(256) gemm_qkv(const float* __restrict__ A,
                                                const float* __restrict__ Wq,
                                                const float* __restrict__ Wk,
                                                const float* __restrict__ Wv,
                                                const float* __restrict__ bq,
                                                const float* __restrict__ bk,
                                                const float* __restrict__ bv,
                                                float* __restrict__ Oq,
                                                float* __restrict__ Ok,
                                                float* __restrict__ Ov,
                                                int M)
{
    int z = blockIdx.z;
    const float* W = (z == 0) ? Wq : (z == 1) ? Wk : Wv;
    const float* b = (z == 0) ? bq : (z == 1) ? bk : bv;
    float*       C = (z == 0) ? Oq : (z == 1) ? Ok : Ov;
    gemm_core<false>(A, W, b, C, M, D, D, blockIdx.y * 128, blockIdx.x * 128);
}

// ---------------- sparse attention: stride-36 K stage, no-max softmax ----------------
#define QCH 64      // queries per block
#define NCH (S / QCH)
#define AKS 36      // K row stride in floats
#define ATTN_SMEM_BYTES ((S1 * AKS + 520 + 16 * 104) * 4)

__global__ void __launch_bounds__(512, 2) attn_sparse()
{
    extern __shared__ float asmem[];
    float* Ks   = asmem;                  // [513][36]
    float* sDen = Ks + S1 * AKS;          // [520] dense-row scratch
    float2* kpAll = (float2*)(sDen + 520);// [16 warps][52] (p, key) pairs
    const int h = blockIdx.x, f = blockIdx.y, qc = blockIdx.z;
    const int tid = threadIdx.x, w = tid >> 5, lane = tid & 31;
    float2* kp = kpAll + w * 52;
    const size_t kvbase = ((size_t)f * S1) * D + h * 32;
    const float scale = 0.17677669529663687f;  // 1/sqrt(32)

    {
        const float4* gk4 = (const float4*)(g_k + kvbase);
        for (int i = tid; i < S1 * 8; i += 512) {
            int s = i >> 3, slot = i & 7;
            *(float4*)&Ks[s * AKS + slot * 4] = __ldg(gk4 + s * 64 + slot);
        }
    }
    __syncthreads();

    const int kq = lane >> 3, dg = lane & 7;

#pragma unroll 1
    for (int j = 0; j < QCH / 16; j++) {
        int q = qc * QCH + w * (QCH / 16) + j;

        const float4* qg = (const float4*)(g_q + kvbase + (size_t)q * D);
        float4 qv[8];
#pragma unroll
        for (int i = 0; i < 8; i++) qv[i] = __ldg(qg + i);

        const int* ip = g_idx + ((size_t)(f * S + q)) * 64;
        int keyA = __ldg(ip + lane);
        int j2 = lane + 32;
        bool validB = (j2 <= 50);
        int keyB = (j2 < 50) ? __ldg(ip + j2) : 512;
        int keyBc = validB ? keyB : 0;

        const float4* ka4 = (const float4*)&Ks[keyA * AKS];
        const float4* kb4 = (const float4*)&Ks[keyBc * AKS];
        float dA0 = 0.f, dA1 = 0.f, dB0 = 0.f, dB1 = 0.f;
#pragma unroll
        for (int i = 0; i < 8; i += 2) {
            float4 q0 = qv[i], q1 = qv[i + 1];
            float4 a0 = ka4[i], a1 = ka4[i + 1];
            float4 b0 = kb4[i], b1 = kb4[i + 1];
            dA0 = fmaf(q0.x, a0.x, dA0); dA0 = fmaf(q0.y, a0.y, dA0);
            dA0 = fmaf(q0.z, a0.z, dA0); dA0 = fmaf(q0.w, a0.w, dA0);
            dA1 = fmaf(q1.x, a1.x, dA1); dA1 = fmaf(q1.y, a1.y, dA1);
            dA1 = fmaf(q1.z, a1.z, dA1); dA1 = fmaf(q1.w, a1.w, dA1);
            dB0 = fmaf(q0.x, b0.x, dB0); dB0 = fmaf(q0.y, b0.y, dB0);
            dB0 = fmaf(q0.z, b0.z, dB0); dB0 = fmaf(q0.w, b0.w, dB0);
            dB1 = fmaf(q1.x, b1.x, dB1); dB1 = fmaf(q1.y, b1.y, dB1);
            dB1 = fmaf(q1.z, b1.z, dB1); dB1 = fmaf(q1.w, b1.w, dB1);
        }
        float sA = (dA0 + dA1) * scale;
        float sB = (dB0 + dB1) * scale;
        // no-max softmax: scores are O(1), exp safe in fp32; softmax identical
        float eA = __expf(sA);
        float eB = validB ? __expf(sB) : 0.f;
        float l = eA + eB;
#pragma unroll
        for (int o = 16; o; o >>= 1) l += __shfl_xor_sync(~0u, l, o);
        float inv = 1.0f / l;

        kp[lane] = make_float2(eA, __int_as_float(keyA));
        if (lane <= 18) kp[32 + lane] = make_float2(eB, __int_as_float(keyBc));
        if (lane == 19) kp[51] = make_float2(0.f, __int_as_float(0));
        __syncwarp();

        float4 acc = make_float4(0.f, 0.f, 0.f, 0.f);
#pragma unroll
        for (int it = 0; it < 13; it++) {
            float2 pk = kp[it * 4 + kq];
            int ky = __float_as_int(pk.y);
            float4 v = *(const float4*)(g_v + kvbase + (size_t)ky * D + dg * 4);
            acc.x = fmaf(pk.x, v.x, acc.x);
            acc.y = fmaf(pk.x, v.y, acc.y);
            acc.z = fmaf(pk.x, v.z, acc.z);
            acc.w = fmaf(pk.x, v.w, acc.w);
        }
#pragma unroll
        for (int o = 8; o <= 16; o <<= 1) {
            acc.x += __shfl_xor_sync(~0u, acc.x, o);
            acc.y += __shfl_xor_sync(~0u, acc.y, o);
            acc.z += __shfl_xor_sync(~0u, acc.z, o);
            acc.w += __shfl_xor_sync(~0u, acc.w, o);
        }
        if (lane < 8) {
            acc.x *= inv; acc.y *= inv; acc.z *= inv; acc.w *= inv;
            *(float4*)(g_attn + kvbase + (size_t)q * D + lane * 4) = acc;
        }
        __syncwarp();
    }

    // dense query-token row: warp 0 of the last chunk (keep max for safety)
    if (qc == NCH - 1 && w == 0) {
        const float4* qg = (const float4*)(g_q + kvbase + (size_t)512 * D);
        float4 qv[8];
#pragma unroll
        for (int i = 0; i < 8; i++) qv[i] = __ldg(qg + i);

        float m = -3.0e38f;
        for (int it = 0; it < 17; it++) {
            int key = it * 32 + lane;
            if (key < S1) {
                const float4* kr = (const float4*)&Ks[key * AKS];
                float d0 = 0.f, d1 = 0.f;
#pragma unroll
                for (int i = 0; i < 8; i += 2) {
                    float4 q0 = qv[i], k40 = kr[i];
                    float4 q1 = qv[i + 1], k41 = kr[i + 1];
                    d0 = fmaf(q0.x, k40.x, d0); d0 = fmaf(q0.y, k40.y, d0);
                    d0 = fmaf(q0.z, k40.z, d0); d0 = fmaf(q0.w, k40.w, d0);
                    d1 = fmaf(q1.x, k41.x, d1); d1 = fmaf(q1.y, k41.y, d1);
                    d1 = fmaf(q1.z, k41.z, d1); d1 = fmaf(q1.w, k41.w, d1);
                }
                float dot = (d0 + d1) * scale;
                sDen[key] = dot;
                m = fmaxf(m, dot);
            }
        }
#pragma unroll
        for (int o = 16; o; o >>= 1) m = fmaxf(m, __shfl_xor_sync(~0u, m, o));
        __syncwarp();
        float l = 0.f;
        for (int it = 0; it < 17; it++) {
            int key = it * 32 + lane;
            if (key < S1) {
                float e = __expf(sDen[key] - m);
                sDen[key] = e;
                l += e;
            }
        }
#pragma unroll
        for (int o = 16; o; o >>= 1) l += __shfl_xor_sync(~0u, l, o);
        float inv = 1.0f / l;
        __syncwarp();
        float a0 = 0.f, a1 = 0.f;
#pragma unroll 2
        for (int key = 0; key < 512; key += 2) {
            a0 = fmaf(sDen[key],     __ldg(g_v + kvbase + (size_t)key * D + lane), a0);
            a1 = fmaf(sDen[key + 1], __ldg(g_v + kvbase + (size_t)(key + 1) * D + lane), a1);
        }
        a0 = fmaf(sDen[512], __ldg(g_v + kvbase + (size_t)512 * D + lane), a0);
        g_attn[kvbase + (size_t)512 * D + lane] = (a0 + a1) * inv;
    }
}

// ---------------- residual add + layernorm: warp per row, float4 ----------------
__global__ void __launch_bounds__(256) add_ln_kernel(float* __restrict__ src,
                                                     const float* __restrict__ y,
                                                     const float* __restrict__ gg,
                                                     const float* __restrict__ bb,
                                                     int M)
{
    const int w = threadIdx.x >> 5, lane = threadIdx.x & 31;
    const int m = blockIdx.x * 8 + w;
    if (m >= M) return;
    float4* zs = (float4*)(src + (size_t)m * D);
    const float4* ys = (const float4*)(y + (size_t)m * D);
    float4 z0 = zs[lane], z1 = zs[lane + 32];
    float4 y0 = ys[lane], y1 = ys[lane + 32];
    z0.x += y0.x; z0.y += y0.y; z0.z += y0.z; z0.w += y0.w;
    z1.x += y1.x; z1.y += y1.y; z1.z += y1.z; z1.w += y1.w;
    float sum = z0.x + z0.y + z0.z + z0.w + z1.x + z1.y + z1.z + z1.w;
    float sq  = z0.x * z0.x + z0.y * z0.y + z0.z * z0.z + z0.w * z0.w
              + z1.x * z1.x + z1.y * z1.y + z1.z * z1.z + z1.w * z1.w;
#pragma unroll
    for (int o = 16; o; o >>= 1) {
        sum += __shfl_xor_sync(~0u, sum, o);
        sq  += __shfl_xor_sync(~0u, sq, o);
    }
    float mean = sum * (1.0f / D);
    float var  = sq * (1.0f / D) - mean * mean;
    float r = rsqrtf(fmaxf(var, 0.f) + 1e-5f);
    const float4* g4 = (const float4*)gg;
    const float4* b4 = (const float4*)bb;
    float4 ga = g4[lane], gb = g4[lane + 32];
    float4 ba = b4[lane], bc = b4[lane + 32];
    z0.x = (z0.x - mean) * r * ga.x + ba.x;
    z0.y = (z0.y - mean) * r * ga.y + ba.y;
    z0.z = (z0.z - mean) * r * ga.z + ba.z;
    z0.w = (z0.w - mean) * r * ga.w + ba.w;
    z1.x = (z1.x - mean) * r * gb.x + bc.x;
    z1.y = (z1.y - mean) * r * gb.y + bc.y;
    z1.z = (z1.z - mean) * r * gb.z + bc.z;
    z1.w = (z1.w - mean) * r * gb.w + bc.w;
    zs[lane] = z0; zs[lane + 32] = z1;
}

// ---------------- gather query token ----------------
__global__ void out_kernel(float* __restrict__ out)
{
    int f = blockIdx.x, c = threadIdx.x;
    out[f * D + c] = g_src[((size_t)(f * S1 + (S1 - 1))) * D + c];
}

// ---------------- host ----------------
extern "C" void kernel_launch(void* const* d_in, const int* in_sizes, int n_in,
                              void* d_out, int out_size)
{
    const float* x   = (const float*)d_in[0];
    const float* qe  = (const float*)d_in[2];
    const float* Wq  = (const float*)d_in[3];  const float* bq  = (const float*)d_in[4];
    const float* Wk  = (const float*)d_in[5];  const float* bk  = (const float*)d_in[6];
    const float* Wv  = (const float*)d_in[7];  const float* bv  = (const float*)d_in[8];
    const float* Wo  = (const float*)d_in[9];  const float* bo  = (const float*)d_in[10];
    const float* l1g = (const float*)d_in[11]; const float* l1b = (const float*)d_in[12];
    const float* l2g = (const float*)d_in[13]; const float* l2b = (const float*)d_in[14];
    const float* W1  = (const float*)d_in[15]; const float* b1  = (const float*)d_in[16];
    const float* W2  = (const float*)d_in[17]; const float* b2  = (const float*)d_in[18];
    float* out = (float*)d_out;

    float *p_src, *p_q, *p_k, *p_v, *p_attn, *p_tmp1;
    cudaGetSymbolAddress((void**)&p_src,  g_src);
    cudaGetSymbolAddress((void**)&p_q,    g_q);
    cudaGetSymbolAddress((void**)&p_k,    g_k);
    cudaGetSymbolAddress((void**)&p_v,    g_v);
    cudaGetSymbolAddress((void**)&p_attn, g_attn);
    cudaGetSymbolAddress((void**)&p_tmp1, g_tmp1);

    cudaFuncSetAttribute(attn_sparse, cudaFuncAttributeMaxDynamicSharedMemorySize,
                         ATTN_SMEM_BYTES);
    cudaFuncSetAttribute(gemm_tc<false>, cudaFuncAttributeMaxDynamicSharedMemorySize,
                         GEMM_SMEM_BYTES);
    cudaFuncSetAttribute(gemm_tc<true>, cudaFuncAttributeMaxDynamicSharedMemorySize,
                         GEMM_SMEM_BYTES);
    cudaFuncSetAttribute(gemm_qkv, cudaFuncAttributeMaxDynamicSharedMemorySize,
                         GEMM_SMEM_BYTES);

    pos_kernel<<<NF * S1, 256>>>(x, qe);
    knn_kernel<<<NF * S / 8, 256>>>(x);

    const int M = NF * S1;
    dim3 gqkv(D / 128, (M + 127) / 128, 3);
    dim3 g256(D / 128, (M + 127) / 128);
    dim3 g1024(DFF / 128, (M + 127) / 128);
    dim3 gattn(8, NF, NCH);
    int  gln = (M + 7) / 8;

    for (int l = 0; l < NL; l++) {
        size_t wo = (size_t)l * D * D;
        gemm_qkv<<<gqkv, 256, GEMM_SMEM_BYTES>>>(p_src, Wq + wo, Wk + wo, Wv + wo,
                                bq + l * D, bk + l * D, bv + l * D,
                                p_q, p_k, p_v, M);
        attn_sparse<<<gattn, 512, ATTN_SMEM_BYTES>>>();
        gemm_tc<false><<<g256, 256, GEMM_SMEM_BYTES>>>(p_attn, Wo + wo, bo + l * D,
                                                       p_tmp1, M, D, D);
        add_ln_kernel<<<gln, 256>>>(p_src, p_tmp1, l1g + l * D, l1b + l * D, M);
        gemm_tc<true><<<g1024, 256, GEMM_SMEM_BYTES>>>(p_src, W1 + (size_t)l * D * DFF,
                                                       b1 + l * DFF, p_tmp1, M, D, DFF);
        gemm_tc<false><<<g256, 256, GEMM_SMEM_BYTES>>>(p_tmp1, W2 + (size_t)l * DFF * D,
                                                       b2 + l * D, p_attn, M, DFF, D);
        add_ln_kernel<<<gln, 256>>>(p_src, p_attn, l2g + l * D, l2b + l * D, M);
    }
    out_kernel<<<NF, 256>>>(out);
}

// round 17
// speedup vs baseline: 1.0643x; 1.0246x over previous
#include <cuda_runtime.h>
#include <math.h>

#define NF   16      // B*F frames
#define S    512
#define S1   513
#define D    256
#define DFF  1024
#define NL   4
#define KNN  50
#define EDIM 42

// ---------------- scratch (device globals; no allocation) ----------------
__device__ float g_src [NF * S1 * D];
__device__ float g_q   [NF * S1 * D];
__device__ float g_k   [NF * S1 * D];
__device__ float g_v   [NF * S1 * D];
__device__ float g_attn[NF * S1 * D];
__device__ float g_tmp1[NF * S1 * DFF];
__device__ int   g_idx [NF * S * 64];     // 50 kNN indices per query (stride 64)

// ---------------- positional encoding + query token ----------------
__global__ void __launch_bounds__(256) pos_kernel(const float* __restrict__ x,
                                                  const float* __restrict__ qe)
{
    int fs = blockIdx.x;              // f*S1 + s
    int f  = fs / S1;
    int s  = fs - f * S1;
    int c  = threadIdx.x;
    float* dst = g_src + (size_t)fs * D;
    if (s == S1 - 1) { dst[c] = qe[c]; return; }
    if (c < 4)       { dst[c] = 0.0f; return; }
    int idx = c - 4;
    int a   = idx / 84;               // axis 0..2
    int r   = idx - a * 84;
    int e   = r >> 1;
    int sc  = r & 1;
    const float bin = 0.002f / 0.015f;
    float xv = x[((size_t)f * S + s) * 3 + a];
    float xq = floorf(xv / bin);
    float dt = powf(10000.0f, (float)e / (float)EDIM);
    float p  = xq / dt;
    dst[c] = sc ? cosf(p) : sinf(p);
}

// ---------------- kNN: warp-per-query register top-50 -> index list ----------------
__global__ void __launch_bounds__(256) knn_kernel(const float* __restrict__ x)
{
    int w = threadIdx.x >> 5, lane = threadIdx.x & 31;
    int qid = blockIdx.x * 8 + w;
    int f = qid >> 9, q = qid & 511;
    const float* xf = x + (size_t)f * S * 3;
    float qx = xf[q * 3], qy = xf[q * 3 + 1], qz = xf[q * 3 + 2];
    float dist[16];
#pragma unroll
    for (int i = 0; i < 16; i++) {
        int k = lane + 32 * i;
        float dx = qx - xf[k * 3];
        float dy = qy - xf[k * 3 + 1];
        float dz = qz - xf[k * 3 + 2];
        dist[i] = __fadd_rn(__fadd_rn(__fmul_rn(dx, dx), __fmul_rn(dy, dy)),
                            __fmul_rn(dz, dz));
    }
    int* orow = g_idx + ((size_t)(f * S + q)) * 64;
    for (int it = 0; it < KNN; it++) {
        float lv = dist[0]; int li = lane;
#pragma unroll
        for (int i = 1; i < 16; i++) {
            if (dist[i] < lv) { lv = dist[i]; li = lane + 32 * i; }
        }
        float v = lv; int idx = li;
#pragma unroll
        for (int o = 16; o; o >>= 1) {
            float ov = __shfl_xor_sync(~0u, v, o);
            int   oi = __shfl_xor_sync(~0u, idx, o);
            if (ov < v || (ov == v && oi < idx)) { v = ov; idx = oi; }
        }
        if (lane == 0) orow[it] = idx;
        int owner = idx & 31, slot = idx >> 5;
        if (lane == owner) {
#pragma unroll
            for (int i = 0; i < 16; i++) if (i == slot) dist[i] = 3.4e38f;
        }
    }
}

// ---------------- common GEMM helpers ----------------
__device__ __forceinline__ void mma_tf32(float c[4], const unsigned a[4],
                                         const unsigned b[2])
{
    asm volatile(
        "mma.sync.aligned.m16n8k8.row.col.f32.tf32.tf32.f32 "
        "{%0,%1,%2,%3},{%4,%5,%6,%7},{%8,%9},{%0,%1,%2,%3};\n"
        : "+f"(c[0]), "+f"(c[1]), "+f"(c[2]), "+f"(c[3])
        : "r"(a[0]), "r"(a[1]), "r"(a[2]), "r"(a[3]), "r"(b[0]), "r"(b[1]));
}

__device__ __forceinline__ void cp_async16(unsigned smem_addr, const void* gptr,
                                           bool valid)
{
    int sz = valid ? 16 : 0;
    asm volatile("cp.async.cg.shared.global [%0], [%1], 16, %2;\n"
                 :: "r"(smem_addr), "l"(gptr), "r"(sz));
}

// ---------------- tf32 GEMM, 2-stage cp.async (R12 proven config) ----------------
#define ASTR 36
#define BSTR 136
#define GEMM_SMEM_BYTES ((2 * 128 * ASTR + 2 * 32 * BSTR) * 4)   // 71680

template <bool RELU>
__device__ __forceinline__ void gemm_core(const float* __restrict__ A,
                                          const float* __restrict__ W,
                                          const float* __restrict__ bias,
                                          float* __restrict__ C,
                                          int M, int K, int N,
                                          int bm, int bn)
{
    extern __shared__ float gsm[];
    float* AsB = gsm;                         // [2][128][36]
    float* BsB = gsm + 2 * 128 * ASTR;        // [2][32][136] k-major
    unsigned As_s = (unsigned)__cvta_generic_to_shared(AsB);
    unsigned Bs_s = (unsigned)__cvta_generic_to_shared(BsB);

    const int tid = threadIdx.x;
    const int wid = tid >> 5, lane = tid & 31;
    const int wm = wid & 3, wn = wid >> 2;    // 4x2 warp grid; tile 32x64
    const int g = lane >> 2, tg = lane & 3;

    const int acr = tid >> 3, acc4 = (tid & 7) * 4;
    const int bcr = tid >> 5, bcc4 = (tid & 31) * 4;

    float c[2][8][4];
#pragma unroll
    for (int mt = 0; mt < 2; mt++)
#pragma unroll
        for (int nt = 0; nt < 8; nt++)
#pragma unroll
            for (int i = 0; i < 4; i++) c[mt][nt][i] = 0.0f;

    {
#pragma unroll
        for (int p = 0; p < 4; p++) {
            int r = acr + 32 * p;
            int gr = bm + r;
            size_t grc = (gr < M) ? (size_t)gr : 0;
            cp_async16(As_s + (unsigned)((r * ASTR + acc4) * 4),
                       A + grc * K + acc4, gr < M);
        }
#pragma unroll
        for (int p = 0; p < 4; p++) {
            int r = bcr + 8 * p;
            cp_async16(Bs_s + (unsigned)((r * BSTR + bcc4) * 4),
                       W + (size_t)r * N + bn + bcc4, true);
        }
        asm volatile("cp.async.commit_group;\n" ::);
    }

    const int nk = K / 32;
    for (int t = 0; t < nk; t++) {
        const int cur = t & 1;
        __syncthreads();
        if (t + 1 < nk) {
            const int k0n = (t + 1) * 32;
            const unsigned abuf = (unsigned)((cur ^ 1) * 128 * ASTR * 4);
            const unsigned bbuf = (unsigned)((cur ^ 1) * 32 * BSTR * 4);
#pragma unroll
            for (int p = 0; p < 4; p++) {
                int r = acr + 32 * p;
                int gr = bm + r;
                size_t grc = (gr < M) ? (size_t)gr : 0;
                cp_async16(As_s + abuf + (unsigned)((r * ASTR + acc4) * 4),
                           A + grc * K + k0n + acc4, gr < M);
            }
#pragma unroll
            for (int p = 0; p < 4; p++) {
                int r = bcr + 8 * p;
                cp_async16(Bs_s + bbuf + (unsigned)((r * BSTR + bcc4) * 4),
                           W + (size_t)(k0n + r) * N + bn + bcc4, true);
            }
            asm volatile("cp.async.commit_group;\n" ::);
            asm volatile("cp.async.wait_group 1;\n" ::);
        } else {
            asm volatile("cp.async.wait_group 0;\n" ::);
        }
        __syncthreads();

        const unsigned* As = (const unsigned*)(AsB + cur * 128 * ASTR);
        const unsigned* Bs = (const unsigned*)(BsB + cur * 32 * BSTR);
#pragma unroll
        for (int kk = 0; kk < 32; kk += 8) {
            unsigned a[2][4], b[8][2];
#pragma unroll
            for (int mt = 0; mt < 2; mt++) {
                int r0 = wm * 32 + mt * 16 + g;
                a[mt][0] = As[r0 * ASTR + kk + tg];
                a[mt][1] = As[(r0 + 8) * ASTR + kk + tg];
                a[mt][2] = As[r0 * ASTR + kk + tg + 4];
                a[mt][3] = As[(r0 + 8) * ASTR + kk + tg + 4];
            }
#pragma unroll
            for (int nt = 0; nt < 8; nt++) {
                int nr = wn * 64 + nt * 8 + g;
                b[nt][0] = Bs[(kk + tg) * BSTR + nr];
                b[nt][1] = Bs[(kk + tg + 4) * BSTR + nr];
            }
#pragma unroll
            for (int mt = 0; mt < 2; mt++)
#pragma unroll
                for (int nt = 0; nt < 8; nt++)
                    mma_tf32(c[mt][nt], a[mt], b[nt]);
        }
    }

#pragma unroll
    for (int mt = 0; mt < 2; mt++) {
#pragma unroll
        for (int half = 0; half < 2; half++) {
            int row = bm + wm * 32 + mt * 16 + g + half * 8;
            if (row >= M) continue;
#pragma unroll
            for (int nt = 0; nt < 8; nt++) {
                int col = bn + wn * 64 + nt * 8 + tg * 2;
                float v0 = c[mt][nt][half * 2 + 0] + bias[col];
                float v1 = c[mt][nt][half * 2 + 1] + bias[col + 1];
                if (RELU) { v0 = fmaxf(v0, 0.f); v1 = fmaxf(v1, 0.f); }
                *(float2*)(C + (size_t)row * N + col) = make_float2(v0, v1);
            }
        }
    }
}

template <bool RELU>
__global__ void __launch_bounds__(256) gemm_tc(const float* __restrict__ A,
                                               const float* __restrict__ W,
                                               const float* __restrict__ bias,
                                               float* __restrict__ C,
                                               int M, int K, int N)
{
    gemm_core<RELU>(A, W, bias, C, M, K, N, blockIdx.y * 128, blockIdx.x * 128);
}

__global__ void __launch_bounds__(256) gemm_qkv(const float* __restrict__ A,
                                                const float* __restrict__ Wq,
                                                const float* __restrict__ Wk,
                                                const float* __restrict__ Wv,
                                                const float* __restrict__ bq,
                                                const float* __restrict__ bk,
                                                const float* __restrict__ bv,
                                                float* __restrict__ Oq,
                                                float* __restrict__ Ok,
                                                float* __restrict__ Ov,
                                                int M)
{
    int z = blockIdx.z;
    const float* W = (z == 0) ? Wq : (z == 1) ? Wk : Wv;
    const float* b = (z == 0) ? bq : (z == 1) ? bk : bv;
    float*       C = (z == 0) ? Oq : (z == 1) ? Ok : Ov;
    gemm_core<false>(A, W, b, C, M, D, D, blockIdx.y * 128, blockIdx.x * 128);
}

// ---------------- fused GEMM (Nx256 full row) + residual + LayerNorm ----------------
// src = LN(src + A*W + bias); BM=32, BN=256, grid.x = ceil(M/32)
#define FBSTR 264
#define GEMMLN_SMEM_BYTES ((2 * 32 * ASTR + 2 * 32 * FBSTR + 320) * 4)   // 78080

__global__ void __launch_bounds__(256) gemm_ln(const float* __restrict__ A,
                                               const float* __restrict__ W,
                                               const float* __restrict__ bias,
                                               float* __restrict__ src,
                                               const float* __restrict__ gg,
                                               const float* __restrict__ bb,
                                               int M, int K)
{
    extern __shared__ float gsm[];
    float* AsB = gsm;                          // [2][32][36]
    float* BsB = gsm + 2 * 32 * ASTR;          // [2][32][264] k-major
    float* red = gsm + 2 * 32 * ASTR + 2 * 32 * FBSTR;  // [32][4][2]
    unsigned As_s = (unsigned)__cvta_generic_to_shared(AsB);
    unsigned Bs_s = (unsigned)__cvta_generic_to_shared(BsB);

    const int tid = threadIdx.x;
    const int wid = tid >> 5, lane = tid & 31;
    const int wm = wid & 1, wn = wid >> 1;     // 2x4 warp grid; tile 16x64
    const int g = lane >> 2, tg = lane & 3;
    const int bm = blockIdx.x * 32;

    const int acr = tid >> 3, acc4 = (tid & 7) * 4;    // A copy
    const int bkr = tid >> 5, bcc4 = (tid & 31) * 4;   // B copy

    float c[8][4];
#pragma unroll
    for (int nt = 0; nt < 8; nt++)
#pragma unroll
        for (int i = 0; i < 4; i++) c[nt][i] = 0.0f;

    // issue tile 0
    {
        int gr = bm + acr;
        size_t grc = (gr < M) ? (size_t)gr : 0;
        cp_async16(As_s + (unsigned)((acr * ASTR + acc4) * 4),
                   A + grc * K + acc4, gr < M);
#pragma unroll
        for (int p = 0; p < 4; p++)
#pragma unroll
            for (int cc = 0; cc < 2; cc++) {
                int r = bkr + 8 * p;
                cp_async16(Bs_s + (unsigned)((r * FBSTR + bcc4 + 128 * cc) * 4),
                           W + (size_t)r * D + bcc4 + 128 * cc, true);
            }
        asm volatile("cp.async.commit_group;\n" ::);
    }

    const int nk = K / 32;
    for (int t = 0; t < nk; t++) {
        const int cur = t & 1;
        __syncthreads();
        if (t + 1 < nk) {
            const int k0n = (t + 1) * 32;
            const unsigned abuf = (unsigned)((cur ^ 1) * 32 * ASTR * 4);
            const unsigned bbuf = (unsigned)((cur ^ 1) * 32 * FBSTR * 4);
            int gr = bm + acr;
            size_t grc = (gr < M) ? (size_t)gr : 0;
            cp_async16(As_s + abuf + (unsigned)((acr * ASTR + acc4) * 4),
                       A + grc * K + k0n + acc4, gr < M);
#pragma unroll
            for (int p = 0; p < 4; p++)
#pragma unroll
                for (int cc = 0; cc < 2; cc++) {
                    int r = bkr + 8 * p;
                    cp_async16(Bs_s + bbuf + (unsigned)((r * FBSTR + bcc4 + 128 * cc) * 4),
                               W + (size_t)(k0n + r) * D + bcc4 + 128 * cc, true);
                }
            asm volatile("cp.async.commit_group;\n" ::);
            asm volatile("cp.async.wait_group 1;\n" ::);
        } else {
            asm volatile("cp.async.wait_group 0;\n" ::);
        }
        __syncthreads();

        const unsigned* As = (const unsigned*)(AsB + cur * 32 * ASTR);
        const unsigned* Bs = (const unsigned*)(BsB + cur * 32 * FBSTR);
#pragma unroll
        for (int kk = 0; kk < 32; kk += 8) {
            unsigned a[4], b[8][2];
            int r0 = wm * 16 + g;
            a[0] = As[r0 * ASTR + kk + tg];
            a[1] = As[(r0 + 8) * ASTR + kk + tg];
            a[2] = As[r0 * ASTR + kk + tg + 4];
            a[3] = As[(r0 + 8) * ASTR + kk + tg + 4];
#pragma unroll
            for (int nt = 0; nt < 8; nt++) {
                int nr = wn * 64 + nt * 8 + g;
                b[nt][0] = Bs[(kk + tg) * FBSTR + nr];
                b[nt][1] = Bs[(kk + tg + 4) * FBSTR + nr];
            }
#pragma unroll
            for (int nt = 0; nt < 8; nt++)
                mma_tf32(c[nt], a, b[nt]);
        }
    }

    // epilogue: residual + LN over the full 256-wide row
    const int rl0 = wm * 16 + g;         // local rows rl0 and rl0+8
    float v[2][8][2];
    float s[2] = {0.f, 0.f}, q2[2] = {0.f, 0.f};
#pragma unroll
    for (int half = 0; half < 2; half++) {
        int row = bm + rl0 + half * 8;
        if (row >= M) continue;
#pragma unroll
        for (int nt = 0; nt < 8; nt++) {
            int col = wn * 64 + nt * 8 + tg * 2;
            float2 sr = *(const float2*)(src + (size_t)row * D + col);
            float v0 = c[nt][half * 2 + 0] + bias[col] + sr.x;
            float v1 = c[nt][half * 2 + 1] + bias[col + 1] + sr.y;
            v[half][nt][0] = v0; v[half][nt][1] = v1;
            s[half] += v0 + v1;
            q2[half] += v0 * v0 + v1 * v1;
        }
    }
#pragma unroll
    for (int o = 1; o <= 2; o <<= 1) {
        s[0]  += __shfl_xor_sync(~0u, s[0], o);
        s[1]  += __shfl_xor_sync(~0u, s[1], o);
        q2[0] += __shfl_xor_sync(~0u, q2[0], o);
        q2[1] += __shfl_xor_sync(~0u, q2[1], o);
    }
    if (tg == 0) {
        red[(rl0)     * 8 + wn * 2 + 0] = s[0];
        red[(rl0)     * 8 + wn * 2 + 1] = q2[0];
        red[(rl0 + 8) * 8 + wn * 2 + 0] = s[1];
        red[(rl0 + 8) * 8 + wn * 2 + 1] = q2[1];
    }
    __syncthreads();
#pragma unroll
    for (int half = 0; half < 2; half++) {
        int rl = rl0 + half * 8;
        int row = bm + rl;
        if (row >= M) continue;
        float sum = 0.f, sqs = 0.f;
#pragma unroll
        for (int i = 0; i < 4; i++) {
            sum += red[rl * 8 + i * 2 + 0];
            sqs += red[rl * 8 + i * 2 + 1];
        }
        float mean = sum * (1.0f / D);
        float var  = sqs * (1.0f / D) - mean * mean;
        float r = rsqrtf(fmaxf(var, 0.f) + 1e-5f);
#pragma unroll
        for (int nt = 0; nt < 8; nt++) {
            int col = wn * 64 + nt * 8 + tg * 2;
            float2 g2 = *(const float2*)(gg + col);
            float2 b2 = *(const float2*)(bb + col);
            float o0 = (v[half][nt][0] - mean) * r * g2.x + b2.x;
            float o1 = (v[half][nt][1] - mean) * r * g2.y + b2.y;
            *(float2*)(src + (size_t)row * D + col) = make_float2(o0, o1);
        }
    }
}

// ---------------- sparse attention: 1024-thread blocks ----------------
#define QCH 128     // queries per block
#define NCH (S / QCH)
#define AKS 36      // K row stride in floats
#define ATTN_SMEM_BYTES ((S1 * AKS + 520 + 32 * 104) * 4)

__global__ void __launch_bounds__(1024, 1) attn_sparse()
{
    extern __shared__ float asmem[];
    float* Ks   = asmem;                  // [513][36]
    float* sDen = Ks + S1 * AKS;          // [520] dense-row scratch
    float2* kpAll = (float2*)(sDen + 520);// [32 warps][52] (p, key) pairs
    const int h = blockIdx.x, f = blockIdx.y, qc = blockIdx.z;
    const int tid = threadIdx.x, w = tid >> 5, lane = tid & 31;
    float2* kp = kpAll + w * 52;
    const size_t kvbase = ((size_t)f * S1) * D + h * 32;
    const float scale = 0.17677669529663687f;  // 1/sqrt(32)

    {
        const float4* gk4 = (const float4*)(g_k + kvbase);
        for (int i = tid; i < S1 * 8; i += 1024) {
            int s = i >> 3, slot = i & 7;
            *(float4*)&Ks[s * AKS + slot * 4] = __ldg(gk4 + s * 64 + slot);
        }
    }
    __syncthreads();

    const int kq = lane >> 3, dg = lane & 7;

#pragma unroll 1
    for (int j = 0; j < QCH / 32; j++) {
        int q = qc * QCH + w * (QCH / 32) + j;

        const float4* qg = (const float4*)(g_q + kvbase + (size_t)q * D);
        float4 qv[8];
#pragma unroll
        for (int i = 0; i < 8; i++) qv[i] = __ldg(qg + i);

        const int* ip = g_idx + ((size_t)(f * S + q)) * 64;
        int keyA = __ldg(ip + lane);
        int j2 = lane + 32;
        bool validB = (j2 <= 50);
        int keyB = (j2 < 50) ? __ldg(ip + j2) : 512;
        int keyBc = validB ? keyB : 0;

        const float4* ka4 = (const float4*)&Ks[keyA * AKS];
        const float4* kb4 = (const float4*)&Ks[keyBc * AKS];
        float dA0 = 0.f, dA1 = 0.f, dB0 = 0.f, dB1 = 0.f;
#pragma unroll
        for (int i = 0; i < 8; i += 2) {
            float4 q0 = qv[i], q1 = qv[i + 1];
            float4 a0 = ka4[i], a1 = ka4[i + 1];
            float4 b0 = kb4[i], b1 = kb4[i + 1];
            dA0 = fmaf(q0.x, a0.x, dA0); dA0 = fmaf(q0.y, a0.y, dA0);
            dA0 = fmaf(q0.z, a0.z, dA0); dA0 = fmaf(q0.w, a0.w, dA0);
            dA1 = fmaf(q1.x, a1.x, dA1); dA1 = fmaf(q1.y, a1.y, dA1);
            dA1 = fmaf(q1.z, a1.z, dA1); dA1 = fmaf(q1.w, a1.w, dA1);
            dB0 = fmaf(q0.x, b0.x, dB0); dB0 = fmaf(q0.y, b0.y, dB0);
            dB0 = fmaf(q0.z, b0.z, dB0); dB0 = fmaf(q0.w, b0.w, dB0);
            dB1 = fmaf(q1.x, b1.x, dB1); dB1 = fmaf(q1.y, b1.y, dB1);
            dB1 = fmaf(q1.z, b1.z, dB1); dB1 = fmaf(q1.w, b1.w, dB1);
        }
        float sA = (dA0 + dA1) * scale;
        float sB = (dB0 + dB1) * scale;
        float eA = __expf(sA);
        float eB = validB ? __expf(sB) : 0.f;
        float l = eA + eB;
#pragma unroll
        for (int o = 16; o; o >>= 1) l += __shfl_xor_sync(~0u, l, o);
        float inv = 1.0f / l;

        kp[lane] = make_float2(eA, __int_as_float(keyA));
        if (lane <= 18) kp[32 + lane] = make_float2(eB, __int_as_float(keyBc));
        if (lane == 19) kp[51] = make_float2(0.f, __int_as_float(0));
        __syncwarp();

        float4 acc = make_float4(0.f, 0.f, 0.f, 0.f);
#pragma unroll
        for (int it = 0; it < 13; it++) {
            float2 pk = kp[it * 4 + kq];
            int ky = __float_as_int(pk.y);
            float4 vv = *(const float4*)(g_v + kvbase + (size_t)ky * D + dg * 4);
            acc.x = fmaf(pk.x, vv.x, acc.x);
            acc.y = fmaf(pk.x, vv.y, acc.y);
            acc.z = fmaf(pk.x, vv.z, acc.z);
            acc.w = fmaf(pk.x, vv.w, acc.w);
        }
#pragma unroll
        for (int o = 8; o <= 16; o <<= 1) {
            acc.x += __shfl_xor_sync(~0u, acc.x, o);
            acc.y += __shfl_xor_sync(~0u, acc.y, o);
            acc.z += __shfl_xor_sync(~0u, acc.z, o);
            acc.w += __shfl_xor_sync(~0u, acc.w, o);
        }
        if (lane < 8) {
            acc.x *= inv; acc.y *= inv; acc.z *= inv; acc.w *= inv;
            *(float4*)(g_attn + kvbase + (size_t)q * D + lane * 4) = acc;
        }
        __syncwarp();
    }

    // dense query-token row: warp 0 of the last chunk (keep max for safety)
    if (qc == NCH - 1 && w == 0) {
        const float4* qg = (const float4*)(g_q + kvbase + (size_t)512 * D);
        float4 qv[8];
#pragma unroll
        for (int i = 0; i < 8; i++) qv[i] = __ldg(qg + i);

        float m = -3.0e38f;
        for (int it = 0; it < 17; it++) {
            int key = it * 32 + lane;
            if (key < S1) {
                const float4* kr = (const float4*)&Ks[key * AKS];
                float d0 = 0.f, d1 = 0.f;
#pragma unroll
                for (int i = 0; i < 8; i += 2) {
                    float4 q0 = qv[i], k40 = kr[i];
                    float4 q1 = qv[i + 1], k41 = kr[i + 1];
                    d0 = fmaf(q0.x, k40.x, d0); d0 = fmaf(q0.y, k40.y, d0);
                    d0 = fmaf(q0.z, k40.z, d0); d0 = fmaf(q0.w, k40.w, d0);
                    d1 = fmaf(q1.x, k41.x, d1); d1 = fmaf(q1.y, k41.y, d1);
                    d1 = fmaf(q1.z, k41.z, d1); d1 = fmaf(q1.w, k41.w, d1);
                }
                float dot = (d0 + d1) * scale;
                sDen[key] = dot;
                m = fmaxf(m, dot);
            }
        }
#pragma unroll
        for (int o = 16; o; o >>= 1) m = fmaxf(m, __shfl_xor_sync(~0u, m, o));
        __syncwarp();
        float l = 0.f;
        for (int it = 0; it < 17; it++) {
            int key = it * 32 + lane;
            if (key < S1) {
                float e = __expf(sDen[key] - m);
                sDen[key] = e;
                l += e;
            }
        }
#pragma unroll
        for (int o = 16; o; o >>= 1) l += __shfl_xor_sync(~0u, l, o);
        float inv = 1.0f / l;
        __syncwarp();
        float a0 = 0.f, a1 = 0.f;
#pragma unroll 2
        for (int key = 0; key < 512; key += 2) {
            a0 = fmaf(sDen[key],     __ldg(g_v + kvbase + (size_t)key * D + lane), a0);
            a1 = fmaf(sDen[key + 1], __ldg(g_v + kvbase + (size_t)(key + 1) * D + lane), a1);
        }
        a0 = fmaf(sDen[512], __ldg(g_v + kvbase + (size_t)512 * D + lane), a0);
        g_attn[kvbase + (size_t)512 * D + lane] = (a0 + a1) * inv;
    }
}

// ---------------- residual add + layernorm (W2 path) ----------------
__global__ void __launch_bounds__(256) add_ln_kernel(float* __restrict__ src,
                                                     const float* __restrict__ y,
                                                     const float* __restrict__ gg,
                                                     const float* __restrict__ bb,
                                                     int M)
{
    const int w = threadIdx.x >> 5, lane = threadIdx.x & 31;
    const int m = blockIdx.x * 8 + w;
    if (m >= M) return;
    float4* zs = (float4*)(src + (size_t)m * D);
    const float4* ys = (const float4*)(y + (size_t)m * D);
    float4 z0 = zs[lane], z1 = zs[lane + 32];
    float4 y0 = ys[lane], y1 = ys[lane + 32];
    z0.x += y0.x; z0.y += y0.y; z0.z += y0.z; z0.w += y0.w;
    z1.x += y1.x; z1.y += y1.y; z1.z += y1.z; z1.w += y1.w;
    float sum = z0.x + z0.y + z0.z + z0.w + z1.x + z1.y + z1.z + z1.w;
    float sq  = z0.x * z0.x + z0.y * z0.y + z0.z * z0.z + z0.w * z0.w
              + z1.x * z1.x + z1.y * z1.y + z1.z * z1.z + z1.w * z1.w;
#pragma unroll
    for (int o = 16; o; o >>= 1) {
        sum += __shfl_xor_sync(~0u, sum, o);
        sq  += __shfl_xor_sync(~0u, sq, o);
    }
    float mean = sum * (1.0f / D);
    float var  = sq * (1.0f / D) - mean * mean;
    float r = rsqrtf(fmaxf(var, 0.f) + 1e-5f);
    const float4* g4 = (const float4*)gg;
    const float4* b4 = (const float4*)bb;
    float4 ga = g4[lane], gb = g4[lane + 32];
    float4 ba = b4[lane], bc = b4[lane + 32];
    z0.x = (z0.x - mean) * r * ga.x + ba.x;
    z0.y = (z0.y - mean) * r * ga.y + ba.y;
    z0.z = (z0.z - mean) * r * ga.z + ba.z;
    z0.w = (z0.w - mean) * r * ga.w + ba.w;
    z1.x = (z1.x - mean) * r * gb.x + bc.x;
    z1.y = (z1.y - mean) * r * gb.y + bc.y;
    z1.z = (z1.z - mean) * r * gb.z + bc.z;
    z1.w = (z1.w - mean) * r * gb.w + bc.w;
    zs[lane] = z0; zs[lane + 32] = z1;
}

// ---------------- gather query token ----------------
__global__ void out_kernel(float* __restrict__ out)
{
    int f = blockIdx.x, c = threadIdx.x;
    out[f * D + c] = g_src[((size_t)(f * S1 + (S1 - 1))) * D + c];
}

// ---------------- host ----------------
extern "C" void kernel_launch(void* const* d_in, const int* in_sizes, int n_in,
                              void* d_out, int out_size)
{
    const float* x   = (const float*)d_in[0];
    const float* qe  = (const float*)d_in[2];
    const float* Wq  = (const float*)d_in[3];  const float* bq  = (const float*)d_in[4];
    const float* Wk  = (const float*)d_in[5];  const float* bk  = (const float*)d_in[6];
    const float* Wv  = (const float*)d_in[7];  const float* bv  = (const float*)d_in[8];
    const float* Wo  = (const float*)d_in[9];  const float* bo  = (const float*)d_in[10];
    const float* l1g = (const float*)d_in[11]; const float* l1b = (const float*)d_in[12];
    const float* l2g = (const float*)d_in[13]; const float* l2b = (const float*)d_in[14];
    const float* W1  = (const float*)d_in[15]; const float* b1  = (const float*)d_in[16];
    const float* W2  = (const float*)d_in[17]; const float* b2  = (const float*)d_in[18];
    float* out = (float*)d_out;

    float *p_src, *p_q, *p_k, *p_v, *p_attn, *p_tmp1;
    cudaGetSymbolAddress((void**)&p_src,  g_src);
    cudaGetSymbolAddress((void**)&p_q,    g_q);
    cudaGetSymbolAddress((void**)&p_k,    g_k);
    cudaGetSymbolAddress((void**)&p_v,    g_v);
    cudaGetSymbolAddress((void**)&p_attn, g_attn);
    cudaGetSymbolAddress((void**)&p_tmp1, g_tmp1);

    cudaFuncSetAttribute(attn_sparse, cudaFuncAttributeMaxDynamicSharedMemorySize,
                         ATTN_SMEM_BYTES);
    cudaFuncSetAttribute(gemm_tc<false>, cudaFuncAttributeMaxDynamicSharedMemorySize,
                         GEMM_SMEM_BYTES);
    cudaFuncSetAttribute(gemm_tc<true>, cudaFuncAttributeMaxDynamicSharedMemorySize,
                         GEMM_SMEM_BYTES);
    cudaFuncSetAttribute(gemm_qkv, cudaFuncAttributeMaxDynamicSharedMemorySize,
                         GEMM_SMEM_BYTES);
    cudaFuncSetAttribute(gemm_ln, cudaFuncAttributeMaxDynamicSharedMemorySize,
                         GEMMLN_SMEM_BYTES);

    pos_kernel<<<NF * S1, 256>>>(x, qe);
    knn_kernel<<<NF * S / 8, 256>>>(x);

    const int M = NF * S1;
    dim3 gqkv(D / 128, (M + 127) / 128, 3);
    dim3 g1024(DFF / 128, (M + 127) / 128);
    dim3 g256(D / 128, (M + 127) / 128);
    dim3 gattn(8, NF, NCH);
    int  gfln = (M + 31) / 32;
    int  gln  = (M + 7) / 8;

    for (int l = 0; l < NL; l++) {
        size_t wo = (size_t)l * D * D;
        gemm_qkv<<<gqkv, 256, GEMM_SMEM_BYTES>>>(p_src, Wq + wo, Wk + wo, Wv + wo,
                                bq + l * D, bk + l * D, bv + l * D,
                                p_q, p_k, p_v, M);
        attn_sparse<<<gattn, 1024, ATTN_SMEM_BYTES>>>();
        gemm_ln<<<gfln, 256, GEMMLN_SMEM_BYTES>>>(p_attn, Wo + wo, bo + l * D,
                                                  p_src, l1g + l * D, l1b + l * D,
                                                  M, D);
        gemm_tc<true><<<g1024, 256, GEMM_SMEM_BYTES>>>(p_src, W1 + (size_t)l * D * DFF,
                                                       b1 + l * DFF, p_tmp1, M, D, DFF);
        gemm_tc<false><<<g256, 256, GEMM_SMEM_BYTES>>>(p_tmp1, W2 + (size_t)l * DFF * D,
                                                       b2 + l * D, p_attn, M, DFF, D);
        add_ln_kernel<<<gln, 256>>>(p_src, p_attn, l2g + l * D, l2b + l * D, M);
    }
    out_kernel<<<NF, 256>>>(out);
}